// round 11
// baseline (speedup 1.0000x reference)
#include <cuda_runtime.h>
#include <cstdint>

// ---------------------------------------------------------------------------
// 64 attention instances: instance i uses contiguous slab [i*65536,(i+1)*65536)
// of each projection viewed as (1024,64).
// Accuracy rules (settled R3-R10): upstream of the mean-threshold mask the
// score pipeline must carry <=~1e-8 deviation. Q/K-proj: 3-way tf32 split
// (h+m+l EXACT representation; 6 MMAs hh+hm+mh+hl+lh+mm, residual ~2^-32).
// QK^T: 4-term split on those Q/K. Downstream smooth paths: V-proj/out
// 3-term, PV 2-term (A hi-only). Stats fused into qk; Z inline in pv.
// ---------------------------------------------------------------------------
#define NORMF 0.04419417382415922f   // 1/sqrt(512)

static __device__ float g_Qp[8192 * 512];
static __device__ float g_Kp[8192 * 512];
static __device__ float g_Vp[8192 * 512];
static __device__ float g_AO[8192 * 512];
static __device__ float g_S[67108864];        // 64*1024*1024 scores
static __device__ float2 g_part[65536 * 32];  // per (row, 32-col block): sum, max
static __device__ float2 g_stats2[65536];     // per row: mean, max

__device__ __forceinline__ float tf32r(float x) {
    uint32_t u;
    asm("cvt.rna.tf32.f32 %0, %1;" : "=r"(u) : "f"(x));
    return __uint_as_float(u);
}

#define MMA8(d, a, b)                                                          \
    asm volatile("mma.sync.aligned.m16n8k8.row.col.f32.tf32.tf32.f32 "         \
                 "{%0,%1,%2,%3}, {%4,%5,%6,%7}, {%8,%9}, {%0,%1,%2,%3};"       \
                 : "+f"((d)[0]), "+f"((d)[1]), "+f"((d)[2]), "+f"((d)[3])      \
                 : "r"((a)[0]), "r"((a)[1]), "r"((a)[2]), "r"((a)[3]),         \
                   "r"((b)[0]), "r"((b)[1]))

// ===========================================================================
// proj6_mm: Q/K projections via 3-way-split tf32 (EXACT representation).
// x = h + m + l with h=tf32(x), m=tf32(x-h), l=(x-h)-m (all exact).
// 6 MMAs: hh, hm, mh, hl, lh, mm. Residual ~2^-32 -> only fp32 reorder noise.
// Block tile 128x64x16, 256 thr, 8 warps (4m x 2n).
// Stage = 3 A-planes (2048 f) + 3 B-planes (1024 f) = 9216 f = 36KB; x2 = 72KB.
// ===========================================================================
__global__ void __launch_bounds__(256, 2) proj6_mm(
    const float* __restrict__ x, const float* __restrict__ y,
    const float* __restrict__ qw, const float* __restrict__ qb,
    const float* __restrict__ kw, const float* __restrict__ kb)
{
    extern __shared__ float sm[];
    const float* A    = blockIdx.z ? y  : x;
    const float* W    = blockIdx.z ? kw : qw;
    const float* bias = blockIdx.z ? kb : qb;
    float* C          = blockIdx.z ? g_Kp : g_Qp;

    const int tid = threadIdx.x;
    const int lane = tid & 31, wid = tid >> 5;
    const int wm = wid & 3, wn = wid >> 2;
    const int row0 = blockIdx.y * 128, col0 = blockIdx.x * 64;
    const float* Ab = A + (size_t)row0 * 512;
    const float* Bb = W + col0;

    int tA[2], rA[2], cA[2];
#pragma unroll
    for (int sl = 0; sl < 2; sl++) {
        int slot = tid + sl * 256;
        tA[sl] = slot >> 5; rA[sl] = (slot & 31) >> 2; cA[sl] = slot & 3;
    }

    float acc[2][4][4];
#pragma unroll
    for (int mt = 0; mt < 2; mt++)
#pragma unroll
        for (int nt = 0; nt < 4; nt++)
#pragma unroll
            for (int e = 0; e < 4; e++) acc[mt][nt][e] = 0.f;

    float ax[2][4], bx[2][2];

    auto LDF = [&](int kb) {
#pragma unroll
        for (int sl = 0; sl < 2; sl++) {
            int tm = tA[sl] & 7, tk = tA[sl] >> 3;
            const float* p = Ab + (size_t)(tm * 16 + rA[sl]) * 512 + kb + tk * 8 + cA[sl];
            const float* q = p + 8 * 512;
            ax[sl][0] = p[0]; ax[sl][1] = q[0];
            ax[sl][2] = p[4]; ax[sl][3] = q[4];
        }
#pragma unroll
        for (int sl = 0; sl < 2; sl++) {
            int tn = tA[sl] & 7, tk = tA[sl] >> 3;
            int n = tn * 8 + rA[sl];
            int kc = kb + tk * 8 + cA[sl];
            const float* p = Bb + (size_t)kc * 512 + n;
            bx[sl][0] = p[0]; bx[sl][1] = p[4 * 512];
        }
    };

    auto STF = [&](int s) {
        float* base = sm + s * 9216;
#pragma unroll
        for (int sl = 0; sl < 2; sl++) {
            float4 h, m, l;
#pragma unroll
            for (int e = 0; e < 4; e++) {
                float v = ax[sl][e];
                float hh = tf32r(v);
                float r = v - hh;
                float mm = tf32r(r);
                float ll = tf32r(r - mm);   // exact (<=3 significant bits)
                (&h.x)[e] = hh; (&m.x)[e] = mm; (&l.x)[e] = ll;
            }
            int slot = tid + sl * 256;
            int off = (slot >> 5) * 128 + (slot & 31) * 4;
            *(float4*)(base + off) = h;
            *(float4*)(base + 2048 + off) = m;
            *(float4*)(base + 4096 + off) = l;
        }
#pragma unroll
        for (int sl = 0; sl < 2; sl++) {
            float2 h, m, l;
#pragma unroll
            for (int e = 0; e < 2; e++) {
                float v = bx[sl][e];
                float hh = tf32r(v);
                float r = v - hh;
                float mm = tf32r(r);
                float ll = tf32r(r - mm);
                (&h.x)[e] = hh; (&m.x)[e] = mm; (&l.x)[e] = ll;
            }
            int slot = tid + sl * 256;
            int off = (slot >> 5) * 64 + (slot & 31) * 2;
            *(float2*)(base + 6144 + off) = h;
            *(float2*)(base + 7168 + off) = m;
            *(float2*)(base + 8192 + off) = l;
        }
    };

    auto CMP = [&](int s) {
        const float* base = sm + s * 9216;
#pragma unroll
        for (int tk = 0; tk < 2; tk++) {
            uint4 ah[2], am[2], al[2];
            uint2 bh[4], bm[4], bl[4];
#pragma unroll
            for (int mt = 0; mt < 2; mt++) {
                int tg = tk * 8 + wm * 2 + mt;
                ah[mt] = *(const uint4*)(base + tg * 128 + lane * 4);
                am[mt] = *(const uint4*)(base + 2048 + tg * 128 + lane * 4);
                al[mt] = *(const uint4*)(base + 4096 + tg * 128 + lane * 4);
            }
#pragma unroll
            for (int nt = 0; nt < 4; nt++) {
                int tg = tk * 8 + wn * 4 + nt;
                bh[nt] = *(const uint2*)(base + 6144 + tg * 64 + lane * 2);
                bm[nt] = *(const uint2*)(base + 7168 + tg * 64 + lane * 2);
                bl[nt] = *(const uint2*)(base + 8192 + tg * 64 + lane * 2);
            }
#pragma unroll
            for (int mt = 0; mt < 2; mt++)
#pragma unroll
                for (int nt = 0; nt < 4; nt++) {
                    MMA8(acc[mt][nt], (&ah[mt].x), (&bh[nt].x));
                    MMA8(acc[mt][nt], (&ah[mt].x), (&bm[nt].x));
                    MMA8(acc[mt][nt], (&am[mt].x), (&bh[nt].x));
                    MMA8(acc[mt][nt], (&ah[mt].x), (&bl[nt].x));
                    MMA8(acc[mt][nt], (&al[mt].x), (&bh[nt].x));
                    MMA8(acc[mt][nt], (&am[mt].x), (&bm[nt].x));
                }
        }
    };

    LDF(0);
    STF(0);
    __syncthreads();
    for (int i = 0; i < 32; i++) {
        if (i + 1 < 32) LDF((i + 1) * 16);
        CMP(i & 1);
        if (i + 1 < 32) STF((i + 1) & 1);
        __syncthreads();
    }

#pragma unroll
    for (int mt = 0; mt < 2; mt++)
#pragma unroll
        for (int nt = 0; nt < 4; nt++) {
            int row = row0 + wm * 32 + mt * 16 + (lane >> 2);
            int col = wn * 32 + nt * 8 + (lane & 3) * 2;
            float b0 = bias[col], b1 = bias[col + 1];
            *(float2*)(C + (size_t)row * 512 + col0 + col) =
                make_float2(acc[mt][nt][0] + b0, acc[mt][nt][1] + b1);
            *(float2*)(C + (size_t)(row + 8) * 512 + col0 + col) =
                make_float2(acc[mt][nt][2] + b0, acc[mt][nt][3] + b1);
        }
}

// ===========================================================================
// qk_tf32: S = (Q @ K^T) * NORM. 4-term split (hh+hl+lh+ll) on fp32-grade Q/K.
// Fused per-(row, 32-col) stat partials. Block tile 128x64x16.
// ===========================================================================
__global__ void __launch_bounds__(256, 2) qk_tf32()
{
    extern __shared__ float sm[];
    const int tid = threadIdx.x;
    const int lane = tid & 31, wid = tid >> 5;
    const int wm = wid & 3, wn = wid >> 2;
    const int inst = blockIdx.z;
    const int row0 = blockIdx.y * 128, col0 = blockIdx.x * 64;
    const float* A = g_Qp + (size_t)inst * 65536 + (size_t)row0 * 64;
    const float* B = g_Kp + (size_t)inst * 65536 + (size_t)col0 * 64;
    float* Sout = g_S + ((size_t)inst << 20) + (size_t)row0 * 1024 + col0;

    int tA[2], rA[2], cA[2];
#pragma unroll
    for (int sl = 0; sl < 2; sl++) {
        int slot = tid + sl * 256;
        tA[sl] = slot >> 5; rA[sl] = (slot & 31) >> 2; cA[sl] = slot & 3;
    }

    float acc[2][4][4];
#pragma unroll
    for (int mt = 0; mt < 2; mt++)
#pragma unroll
        for (int nt = 0; nt < 4; nt++)
#pragma unroll
            for (int e = 0; e < 4; e++) acc[mt][nt][e] = 0.f;

    float ax[2][4], bx[2][2];

    auto LDF = [&](int kb) {
#pragma unroll
        for (int sl = 0; sl < 2; sl++) {
            int tm = tA[sl] & 7, tk = tA[sl] >> 3;
            const float* p = A + (size_t)(tm * 16 + rA[sl]) * 64 + kb + tk * 8 + cA[sl];
            const float* q = p + 8 * 64;
            ax[sl][0] = p[0]; ax[sl][1] = q[0];
            ax[sl][2] = p[4]; ax[sl][3] = q[4];
        }
#pragma unroll
        for (int sl = 0; sl < 2; sl++) {
            int tn = tA[sl] & 7, tk = tA[sl] >> 3;
            const float* p = B + (size_t)(tn * 8 + rA[sl]) * 64 + kb + tk * 8 + cA[sl];
            bx[sl][0] = p[0]; bx[sl][1] = p[4];
        }
    };

    auto STF = [&](int s) {
        float* base = sm + s * 6144;
#pragma unroll
        for (int sl = 0; sl < 2; sl++) {
            float4 h, l;
            h.x = tf32r(ax[sl][0]); l.x = tf32r(ax[sl][0] - h.x);
            h.y = tf32r(ax[sl][1]); l.y = tf32r(ax[sl][1] - h.y);
            h.z = tf32r(ax[sl][2]); l.z = tf32r(ax[sl][2] - h.z);
            h.w = tf32r(ax[sl][3]); l.w = tf32r(ax[sl][3] - h.w);
            int slot = tid + sl * 256;
            int off = (slot >> 5) * 128 + (slot & 31) * 4;
            *(float4*)(base + off) = h;
            *(float4*)(base + 2048 + off) = l;
        }
#pragma unroll
        for (int sl = 0; sl < 2; sl++) {
            float2 h, l;
            h.x = tf32r(bx[sl][0]); l.x = tf32r(bx[sl][0] - h.x);
            h.y = tf32r(bx[sl][1]); l.y = tf32r(bx[sl][1] - h.y);
            int slot = tid + sl * 256;
            int off = (slot >> 5) * 64 + (slot & 31) * 2;
            *(float2*)(base + 4096 + off) = h;
            *(float2*)(base + 5120 + off) = l;
        }
    };

    auto CMP = [&](int s) {
        const float* base = sm + s * 6144;
#pragma unroll
        for (int tk = 0; tk < 2; tk++) {
            uint4 ah[2], al[2];
            uint2 bh[4], bl[4];
#pragma unroll
            for (int mt = 0; mt < 2; mt++) {
                int tg = tk * 8 + wm * 2 + mt;
                ah[mt] = *(const uint4*)(base + tg * 128 + lane * 4);
                al[mt] = *(const uint4*)(base + 2048 + tg * 128 + lane * 4);
            }
#pragma unroll
            for (int nt = 0; nt < 4; nt++) {
                int tg = tk * 8 + wn * 4 + nt;
                bh[nt] = *(const uint2*)(base + 4096 + tg * 64 + lane * 2);
                bl[nt] = *(const uint2*)(base + 5120 + tg * 64 + lane * 2);
            }
#pragma unroll
            for (int mt = 0; mt < 2; mt++)
#pragma unroll
                for (int nt = 0; nt < 4; nt++) {
                    MMA8(acc[mt][nt], (&ah[mt].x), (&bh[nt].x));
                    MMA8(acc[mt][nt], (&ah[mt].x), (&bl[nt].x));
                    MMA8(acc[mt][nt], (&al[mt].x), (&bh[nt].x));
                    MMA8(acc[mt][nt], (&al[mt].x), (&bl[nt].x));
                }
        }
    };

    LDF(0);
    STF(0);
    __syncthreads();
    for (int i = 0; i < 4; i++) {
        if (i + 1 < 4) LDF((i + 1) * 16);
        CMP(i & 1);
        if (i + 1 < 4) STF((i + 1) & 1);
        __syncthreads();
    }

#pragma unroll
    for (int mt = 0; mt < 2; mt++) {
#pragma unroll
        for (int half = 0; half < 2; half++) {
            int row = wm * 32 + mt * 16 + (lane >> 2) + half * 8;
            float v[8];
#pragma unroll
            for (int nt = 0; nt < 4; nt++) {
                v[nt * 2 + 0] = acc[mt][nt][half * 2 + 0] * NORMF;
                v[nt * 2 + 1] = acc[mt][nt][half * 2 + 1] * NORMF;
                int col = wn * 32 + nt * 8 + (lane & 3) * 2;
                *(float2*)(Sout + (size_t)row * 1024 + col) =
                    make_float2(v[nt * 2], v[nt * 2 + 1]);
            }
            float s8 = ((v[0] + v[1]) + (v[2] + v[3])) + ((v[4] + v[5]) + (v[6] + v[7]));
            float m8 = fmaxf(fmaxf(fmaxf(v[0], v[1]), fmaxf(v[2], v[3])),
                             fmaxf(fmaxf(v[4], v[5]), fmaxf(v[6], v[7])));
#pragma unroll
            for (int o = 1; o < 4; o <<= 1) {
                s8 += __shfl_xor_sync(0xffffffffu, s8, o);
                m8 = fmaxf(m8, __shfl_xor_sync(0xffffffffu, m8, o));
            }
            if ((lane & 3) == 0)
                g_part[((size_t)inst * 1024 + row0 + row) * 32 + blockIdx.x * 2 + wn] =
                    make_float2(s8, m8);
        }
    }
}

// Coalesced reduce: 8 threads/row, float4 loads, shfl combine.
__global__ void __launch_bounds__(256) reduce_stats()
{
    int g = blockIdx.x * 256 + threadIdx.x;
    int row = g >> 3, sub = g & 7;
    const float4* p = (const float4*)(g_part + (size_t)row * 32) + sub * 2;
    float4 v0 = p[0], v1 = p[1];
    float s = (v0.x + v0.z) + (v1.x + v1.z);
    float m = fmaxf(fmaxf(v0.y, v0.w), fmaxf(v1.y, v1.w));
#pragma unroll
    for (int o = 1; o < 8; o <<= 1) {
        s += __shfl_xor_sync(0xffffffffu, s, o);
        m = fmaxf(m, __shfl_xor_sync(0xffffffffu, m, o));
    }
    if (sub == 0)
        g_stats2[row] = make_float2(s * (1.0f / 1024.0f), m);
}

// ===========================================================================
// mm_body: 3xTF32 split GEMM (V-proj, out). B is K x 64 (B[k][n]).
// ===========================================================================
__device__ __forceinline__ void mm_body(
    const float* __restrict__ A, int lda,
    const float* __restrict__ B, int ldb,
    const float* __restrict__ bias,
    float* __restrict__ C, int ldc, int ktot)
{
    extern __shared__ float sm[];
    const int tid = threadIdx.x;
    const int lane = tid & 31, wid = tid >> 5;
    const int wm = wid & 3, wn = wid >> 2;

    int tA[2], rA[2], cA[2];
#pragma unroll
    for (int sl = 0; sl < 2; sl++) {
        int slot = tid + sl * 256;
        tA[sl] = slot >> 5; rA[sl] = (slot & 31) >> 2; cA[sl] = slot & 3;
    }

    float acc[2][4][4];
#pragma unroll
    for (int mt = 0; mt < 2; mt++)
#pragma unroll
        for (int nt = 0; nt < 4; nt++)
#pragma unroll
            for (int e = 0; e < 4; e++) acc[mt][nt][e] = 0.f;

    float ax[2][4], bx[2][2];

    auto LDF = [&](int kb) {
#pragma unroll
        for (int sl = 0; sl < 2; sl++) {
            int tm = tA[sl] & 7, tk = tA[sl] >> 3;
            const float* p = A + (size_t)(tm * 16 + rA[sl]) * lda + kb + tk * 8 + cA[sl];
            const float* q = p + 8 * (size_t)lda;
            ax[sl][0] = p[0]; ax[sl][1] = q[0];
            ax[sl][2] = p[4]; ax[sl][3] = q[4];
        }
#pragma unroll
        for (int sl = 0; sl < 2; sl++) {
            int tn = tA[sl] & 7, tk = tA[sl] >> 3;
            int n = tn * 8 + rA[sl];
            int kc = kb + tk * 8 + cA[sl];
            const float* p = B + (size_t)kc * ldb + n;
            bx[sl][0] = p[0]; bx[sl][1] = p[4 * (size_t)ldb];
        }
    };

    auto STF = [&](int s) {
        float* base = sm + s * 6144;
#pragma unroll
        for (int sl = 0; sl < 2; sl++) {
            float4 h, l;
            h.x = tf32r(ax[sl][0]); l.x = tf32r(ax[sl][0] - h.x);
            h.y = tf32r(ax[sl][1]); l.y = tf32r(ax[sl][1] - h.y);
            h.z = tf32r(ax[sl][2]); l.z = tf32r(ax[sl][2] - h.z);
            h.w = tf32r(ax[sl][3]); l.w = tf32r(ax[sl][3] - h.w);
            int slot = tid + sl * 256;
            int off = (slot >> 5) * 128 + (slot & 31) * 4;
            *(float4*)(base + off) = h;
            *(float4*)(base + 2048 + off) = l;
        }
#pragma unroll
        for (int sl = 0; sl < 2; sl++) {
            float2 h, l;
            h.x = tf32r(bx[sl][0]); l.x = tf32r(bx[sl][0] - h.x);
            h.y = tf32r(bx[sl][1]); l.y = tf32r(bx[sl][1] - h.y);
            int slot = tid + sl * 256;
            int off = (slot >> 5) * 64 + (slot & 31) * 2;
            *(float2*)(base + 4096 + off) = h;
            *(float2*)(base + 5120 + off) = l;
        }
    };

    auto CMP = [&](int s) {
        const float* base = sm + s * 6144;
#pragma unroll
        for (int tk = 0; tk < 2; tk++) {
            uint4 ah[2], al[2];
            uint2 bh[4], bl[4];
#pragma unroll
            for (int mt = 0; mt < 2; mt++) {
                int tg = tk * 8 + wm * 2 + mt;
                ah[mt] = *(const uint4*)(base + tg * 128 + lane * 4);
                al[mt] = *(const uint4*)(base + 2048 + tg * 128 + lane * 4);
            }
#pragma unroll
            for (int nt = 0; nt < 4; nt++) {
                int tg = tk * 8 + wn * 4 + nt;
                bh[nt] = *(const uint2*)(base + 4096 + tg * 64 + lane * 2);
                bl[nt] = *(const uint2*)(base + 5120 + tg * 64 + lane * 2);
            }
#pragma unroll
            for (int mt = 0; mt < 2; mt++)
#pragma unroll
                for (int nt = 0; nt < 4; nt++) {
                    MMA8(acc[mt][nt], (&ah[mt].x), (&bh[nt].x));
                    MMA8(acc[mt][nt], (&ah[mt].x), (&bl[nt].x));
                    MMA8(acc[mt][nt], (&al[mt].x), (&bh[nt].x));
                }
        }
    };

    const int nk = ktot / 16;
    LDF(0);
    STF(0);
    __syncthreads();
    for (int i = 0; i < nk; i++) {
        if (i + 1 < nk) LDF((i + 1) * 16);
        CMP(i & 1);
        if (i + 1 < nk) STF((i + 1) & 1);
        __syncthreads();
    }

#pragma unroll
    for (int mt = 0; mt < 2; mt++)
#pragma unroll
        for (int nt = 0; nt < 4; nt++) {
            int row = wm * 32 + mt * 16 + (lane >> 2);
            int col = wn * 32 + nt * 8 + (lane & 3) * 2;
            float b0 = bias[col], b1 = bias[col + 1];
            *(float2*)(C + (size_t)row * ldc + col) =
                make_float2(acc[mt][nt][0] + b0, acc[mt][nt][1] + b1);
            *(float2*)(C + (size_t)(row + 8) * ldc + col) =
                make_float2(acc[mt][nt][2] + b0, acc[mt][nt][3] + b1);
        }
}

__global__ void __launch_bounds__(256, 2) projv_mm(
    const float* __restrict__ y,
    const float* __restrict__ vw, const float* __restrict__ vb)
{
    int row0 = blockIdx.y * 128, col0 = blockIdx.x * 64;
    mm_body(y + (size_t)row0 * 512, 512, vw + col0, 512,
            vb + col0, g_Vp + (size_t)row0 * 512 + col0, 512, 512);
}

__global__ void __launch_bounds__(256, 2) out_mm(
    const float* __restrict__ ow, const float* __restrict__ ob,
    float* __restrict__ out)
{
    int row0 = blockIdx.y * 128, col0 = blockIdx.x * 64;
    mm_body(g_AO + (size_t)row0 * 512, 512, ow + col0, 512,
            ob + col0, out + (size_t)row0 * 512 + col0, 512, 512);
}

// ---------------------------------------------------------------------------
// pv_mm: O = softmax_masked(S) @ V. A hi-only x B hi/lo (2 MMAs per (mt,nt)).
// R8-proven 2-stage pipeline. Inline Z accumulation; 1/Z in epilogue.
// Stage = A-hi(2048) | B-hi(1024) | B-lo(1024) floats = 16KB; 2 stages 32KB.
// ---------------------------------------------------------------------------
__global__ void __launch_bounds__(256, 2) pv_mm()
{
    extern __shared__ float sm[];
    __shared__ float z_sm[128];
    const int tid = threadIdx.x;
    const int lane = tid & 31, wid = tid >> 5;
    const int wm = wid & 3, wn = wid >> 2;
    const int inst = blockIdx.z, row0 = blockIdx.y * 128;
    const float* A = g_S + ((size_t)inst << 20) + (size_t)row0 * 1024;
    const float* B = g_Vp + (size_t)inst * 65536;
    float* C = g_AO + (size_t)inst * 65536 + (size_t)row0 * 64;
    const float2* st = g_stats2 + inst * 1024 + row0;

    int tA[2], rA[2], cA[2], m0s[2];
    float2 st0[2], st1[2];
#pragma unroll
    for (int sl = 0; sl < 2; sl++) {
        int slot = tid + sl * 256;
        tA[sl] = slot >> 5; rA[sl] = (slot & 31) >> 2; cA[sl] = slot & 3;
        m0s[sl] = (tA[sl] & 7) * 16 + rA[sl];
        st0[sl] = st[m0s[sl]];
        st1[sl] = st[m0s[sl] + 8];
    }

    if (tid < 128) z_sm[tid] = 0.f;

    float acc[2][4][4];
#pragma unroll
    for (int mt = 0; mt < 2; mt++)
#pragma unroll
        for (int nt = 0; nt < 4; nt++)
#pragma unroll
            for (int e = 0; e < 4; e++) acc[mt][nt][e] = 0.f;

    float z0[2] = {0.f, 0.f}, z1[2] = {0.f, 0.f};
    float ax[2][4], bx[2][2];

    auto LDF = [&](int kb) {
#pragma unroll
        for (int sl = 0; sl < 2; sl++) {
            int tk = tA[sl] >> 3;
            const float* p = A + (size_t)m0s[sl] * 1024 + kb + tk * 8 + cA[sl];
            const float* q = p + 8 * 1024;
            ax[sl][0] = p[0]; ax[sl][1] = q[0];
            ax[sl][2] = p[4]; ax[sl][3] = q[4];
        }
#pragma unroll
        for (int sl = 0; sl < 2; sl++) {
            int tn = tA[sl] & 7, tk = tA[sl] >> 3;
            int n = tn * 8 + rA[sl];
            int kc = kb + tk * 8 + cA[sl];
            const float* p = B + (size_t)kc * 64 + n;
            bx[sl][0] = p[0]; bx[sl][1] = p[4 * 64];
        }
    };

    auto STF = [&](int s) {
        float* base = sm + s * 4096;
#pragma unroll
        for (int sl = 0; sl < 2; sl++) {
            float p0 = (ax[sl][0] > st0[sl].x) ? __expf(ax[sl][0] - st0[sl].y) : 0.f;
            float p1 = (ax[sl][1] > st1[sl].x) ? __expf(ax[sl][1] - st1[sl].y) : 0.f;
            float p2 = (ax[sl][2] > st0[sl].x) ? __expf(ax[sl][2] - st0[sl].y) : 0.f;
            float p3 = (ax[sl][3] > st1[sl].x) ? __expf(ax[sl][3] - st1[sl].y) : 0.f;
            z0[sl] += p0 + p2;
            z1[sl] += p1 + p3;
            float4 h;
            h.x = tf32r(p0); h.y = tf32r(p1); h.z = tf32r(p2); h.w = tf32r(p3);
            int slot = tid + sl * 256;
            int off = (slot >> 5) * 128 + (slot & 31) * 4;
            *(float4*)(base + off) = h;
        }
#pragma unroll
        for (int sl = 0; sl < 2; sl++) {
            float2 h, l;
            h.x = tf32r(bx[sl][0]); l.x = tf32r(bx[sl][0] - h.x);
            h.y = tf32r(bx[sl][1]); l.y = tf32r(bx[sl][1] - h.y);
            int slot = tid + sl * 256;
            int off = (slot >> 5) * 64 + (slot & 31) * 2;
            *(float2*)(base + 2048 + off) = h;
            *(float2*)(base + 3072 + off) = l;
        }
    };

    auto CMP = [&](int s) {
        const float* base = sm + s * 4096;
#pragma unroll
        for (int tk = 0; tk < 2; tk++) {
            uint4 ah[2];
            uint2 bh[4], bl[4];
#pragma unroll
            for (int mt = 0; mt < 2; mt++) {
                int tg = tk * 8 + wm * 2 + mt;
                ah[mt] = *(const uint4*)(base + tg * 128 + lane * 4);
            }
#pragma unroll
            for (int nt = 0; nt < 4; nt++) {
                int tg = tk * 8 + wn * 4 + nt;
                bh[nt] = *(const uint2*)(base + 2048 + tg * 64 + lane * 2);
                bl[nt] = *(const uint2*)(base + 3072 + tg * 64 + lane * 2);
            }
#pragma unroll
            for (int mt = 0; mt < 2; mt++)
#pragma unroll
                for (int nt = 0; nt < 4; nt++) {
                    MMA8(acc[mt][nt], (&ah[mt].x), (&bh[nt].x));
                    MMA8(acc[mt][nt], (&ah[mt].x), (&bl[nt].x));
                }
        }
    };

    LDF(0);
    STF(0);
    __syncthreads();
    for (int i = 0; i < 64; i++) {
        if (i + 1 < 64) LDF((i + 1) * 16);
        CMP(i & 1);
        if (i + 1 < 64) STF((i + 1) & 1);
        __syncthreads();
    }

#pragma unroll
    for (int sl = 0; sl < 2; sl++) {
        atomicAdd(&z_sm[m0s[sl]], z0[sl]);
        atomicAdd(&z_sm[m0s[sl] + 8], z1[sl]);
    }
    __syncthreads();

#pragma unroll
    for (int mt = 0; mt < 2; mt++)
#pragma unroll
        for (int nt = 0; nt < 4; nt++) {
            int row = wm * 32 + mt * 16 + (lane >> 2);
            int col = wn * 32 + nt * 8 + (lane & 3) * 2;
            float iz0 = 1.0f / z_sm[row];
            float iz1 = 1.0f / z_sm[row + 8];
            *(float2*)(C + (size_t)row * 64 + col) =
                make_float2(acc[mt][nt][0] * iz0, acc[mt][nt][1] * iz0);
            *(float2*)(C + (size_t)(row + 8) * 64 + col) =
                make_float2(acc[mt][nt][2] * iz1, acc[mt][nt][3] * iz1);
        }
}

// ---------------------------------------------------------------------------
extern "C" void kernel_launch(void* const* d_in, const int* in_sizes, int n_in,
                              void* d_out, int out_size)
{
    const float* x  = (const float*)d_in[0];
    const float* y  = (const float*)d_in[1];
    const float* qw = (const float*)d_in[2];
    const float* qb = (const float*)d_in[3];
    const float* kw = (const float*)d_in[4];
    const float* kb = (const float*)d_in[5];
    const float* vw = (const float*)d_in[6];
    const float* vb = (const float*)d_in[7];
    const float* ow = (const float*)d_in[8];
    const float* ob = (const float*)d_in[9];
    float* out = (float*)d_out;

    const int SMB  = 49152;    // mm_body/qk: 2 stages * 24KB
    const int SM6  = 73728;    // proj6: 2 stages * 36KB
    const int SMPV = 32768;    // pv: 2 stages * 16KB
    cudaFuncSetAttribute(proj6_mm, cudaFuncAttributeMaxDynamicSharedMemorySize, SM6);
    cudaFuncSetAttribute(qk_tf32,  cudaFuncAttributeMaxDynamicSharedMemorySize, SMB);
    cudaFuncSetAttribute(projv_mm, cudaFuncAttributeMaxDynamicSharedMemorySize, SMB);
    cudaFuncSetAttribute(pv_mm,    cudaFuncAttributeMaxDynamicSharedMemorySize, SMPV);
    cudaFuncSetAttribute(out_mm,   cudaFuncAttributeMaxDynamicSharedMemorySize, SMB);

    proj6_mm<<<dim3(8, 64, 2), 256, SM6>>>(x, y, qw, qb, kw, kb);
    projv_mm<<<dim3(8, 64, 1), 256, SMB>>>(y, vw, vb);
    qk_tf32<<<dim3(16, 8, 64), 256, SMB>>>();
    reduce_stats<<<2048, 256>>>();
    pv_mm<<<dim3(1, 8, 64), 256, SMPV>>>();
    out_mm<<<dim3(8, 64, 1), 256, SMB>>>(ow, ob, out);
}

// round 12
// speedup vs baseline: 1.1163x; 1.1163x over previous
#include <cuda_runtime.h>
#include <cstdint>

// ---------------------------------------------------------------------------
// 64 attention instances: instance i uses contiguous slab [i*65536,(i+1)*65536)
// of each projection viewed as (1024,64).
// Accuracy laws (R3-R11, empirically settled):
//  - Q/K proj: EXACT ascending-k fp32 FFMA, bit-matching reference. Any
//    MMA-based proj (even representation-exact splits) injects ~1e-7 reorder
//    noise -> mask flips -> ~8e-4 rel_err. Frozen as FFMA.
//  - QK^T: 4-term tf32 split (hh+hl+lh+ll) on exact Q/K: clean.
//  - V-proj/out: 3-term split; PV: 2-term (A hi-only) -> ~3.4e-4 smooth.
// This round: fuse Q/K/V projections into ONE 1536-CTA launch (tail waste
// 2x1.73-wave -> 5.2-wave). All numeric paths bit-identical to R8.
// ---------------------------------------------------------------------------
#define NORMF 0.04419417382415922f   // 1/sqrt(512)

static __device__ float g_Qp[8192 * 512];
static __device__ float g_Kp[8192 * 512];
static __device__ float g_Vp[8192 * 512];
static __device__ float g_AO[8192 * 512];
static __device__ float g_S[67108864];        // 64*1024*1024 scores
static __device__ float2 g_part[65536 * 32];  // per (row, 32-col block): sum, max
static __device__ float2 g_stats2[65536];     // per row: mean, max

#define FMA2(d, a, b, c) \
    asm("fma.rn.f32x2 %0, %1, %2, %3;" : "=l"(d) : "l"(a), "l"(b), "l"(c))
#define PACK2(d, x) \
    asm("mov.b64 %0, {%1, %1};" : "=l"(d) : "r"(x))
#define UNPK2(lo, hi, d) \
    asm("mov.b64 {%0, %1}, %2;" : "=r"(lo), "=r"(hi) : "l"(d))

__device__ __forceinline__ float tf32r(float x) {
    uint32_t u;
    asm("cvt.rna.tf32.f32 %0, %1;" : "=r"(u) : "f"(x));
    return __uint_as_float(u);
}

#define MMA8(d, a, b)                                                          \
    asm volatile("mma.sync.aligned.m16n8k8.row.col.f32.tf32.tf32.f32 "         \
                 "{%0,%1,%2,%3}, {%4,%5,%6,%7}, {%8,%9}, {%0,%1,%2,%3};"       \
                 : "+f"((d)[0]), "+f"((d)[1]), "+f"((d)[2]), "+f"((d)[3])      \
                 : "r"((a)[0]), "r"((a)[1]), "r"((a)[2]), "r"((a)[3]),         \
                   "r"((b)[0]), "r"((b)[1]))

// ===========================================================================
// mm_body: 3xTF32 split GEMM (V-proj, out). B is K x 64 (B[k][n]).
// Block tile 128x64x16, 256 thr, 8 warps (4m x 2n). Stage 24KB; 2 stages.
// ===========================================================================
__device__ __forceinline__ void mm_body(
    const float* __restrict__ A, int lda,
    const float* __restrict__ B, int ldb,
    const float* __restrict__ bias,
    float* __restrict__ C, int ldc, int ktot)
{
    extern __shared__ float sm[];
    const int tid = threadIdx.x;
    const int lane = tid & 31, wid = tid >> 5;
    const int wm = wid & 3, wn = wid >> 2;

    int tA[2], rA[2], cA[2];
#pragma unroll
    for (int sl = 0; sl < 2; sl++) {
        int slot = tid + sl * 256;
        tA[sl] = slot >> 5; rA[sl] = (slot & 31) >> 2; cA[sl] = slot & 3;
    }

    float acc[2][4][4];
#pragma unroll
    for (int mt = 0; mt < 2; mt++)
#pragma unroll
        for (int nt = 0; nt < 4; nt++)
#pragma unroll
            for (int e = 0; e < 4; e++) acc[mt][nt][e] = 0.f;

    float ax[2][4], bx[2][2];

    auto LDF = [&](int kb) {
#pragma unroll
        for (int sl = 0; sl < 2; sl++) {
            int tm = tA[sl] & 7, tk = tA[sl] >> 3;
            const float* p = A + (size_t)(tm * 16 + rA[sl]) * lda + kb + tk * 8 + cA[sl];
            const float* q = p + 8 * (size_t)lda;
            ax[sl][0] = p[0]; ax[sl][1] = q[0];
            ax[sl][2] = p[4]; ax[sl][3] = q[4];
        }
#pragma unroll
        for (int sl = 0; sl < 2; sl++) {
            int tn = tA[sl] & 7, tk = tA[sl] >> 3;
            int n = tn * 8 + rA[sl];
            int kc = kb + tk * 8 + cA[sl];
            const float* p = B + (size_t)kc * ldb + n;
            bx[sl][0] = p[0]; bx[sl][1] = p[4 * (size_t)ldb];
        }
    };

    auto STF = [&](int s) {
        float* base = sm + s * 6144;
#pragma unroll
        for (int sl = 0; sl < 2; sl++) {
            float4 h, l;
            h.x = tf32r(ax[sl][0]); l.x = tf32r(ax[sl][0] - h.x);
            h.y = tf32r(ax[sl][1]); l.y = tf32r(ax[sl][1] - h.y);
            h.z = tf32r(ax[sl][2]); l.z = tf32r(ax[sl][2] - h.z);
            h.w = tf32r(ax[sl][3]); l.w = tf32r(ax[sl][3] - h.w);
            int slot = tid + sl * 256;
            int off = (slot >> 5) * 128 + (slot & 31) * 4;
            *(float4*)(base + off) = h;
            *(float4*)(base + 2048 + off) = l;
        }
#pragma unroll
        for (int sl = 0; sl < 2; sl++) {
            float2 h, l;
            h.x = tf32r(bx[sl][0]); l.x = tf32r(bx[sl][0] - h.x);
            h.y = tf32r(bx[sl][1]); l.y = tf32r(bx[sl][1] - h.y);
            int slot = tid + sl * 256;
            int off = (slot >> 5) * 64 + (slot & 31) * 2;
            *(float2*)(base + 4096 + off) = h;
            *(float2*)(base + 5120 + off) = l;
        }
    };

    auto CMP = [&](int s) {
        const float* base = sm + s * 6144;
#pragma unroll
        for (int tk = 0; tk < 2; tk++) {
            uint4 ah[2], al[2];
            uint2 bh[4], bl[4];
#pragma unroll
            for (int mt = 0; mt < 2; mt++) {
                int tg = tk * 8 + wm * 2 + mt;
                ah[mt] = *(const uint4*)(base + tg * 128 + lane * 4);
                al[mt] = *(const uint4*)(base + 2048 + tg * 128 + lane * 4);
            }
#pragma unroll
            for (int nt = 0; nt < 4; nt++) {
                int tg = tk * 8 + wn * 4 + nt;
                bh[nt] = *(const uint2*)(base + 4096 + tg * 64 + lane * 2);
                bl[nt] = *(const uint2*)(base + 5120 + tg * 64 + lane * 2);
            }
#pragma unroll
            for (int mt = 0; mt < 2; mt++)
#pragma unroll
                for (int nt = 0; nt < 4; nt++) {
                    MMA8(acc[mt][nt], (&ah[mt].x), (&bh[nt].x));
                    MMA8(acc[mt][nt], (&ah[mt].x), (&bl[nt].x));
                    MMA8(acc[mt][nt], (&al[mt].x), (&bh[nt].x));
                }
        }
    };

    const int nk = ktot / 16;
    LDF(0);
    STF(0);
    __syncthreads();
    for (int i = 0; i < nk; i++) {
        if (i + 1 < nk) LDF((i + 1) * 16);
        CMP(i & 1);
        if (i + 1 < nk) STF((i + 1) & 1);
        __syncthreads();
    }

#pragma unroll
    for (int mt = 0; mt < 2; mt++)
#pragma unroll
        for (int nt = 0; nt < 4; nt++) {
            int row = wm * 32 + mt * 16 + (lane >> 2);
            int col = wn * 32 + nt * 8 + (lane & 3) * 2;
            float b0 = bias[col], b1 = bias[col + 1];
            *(float2*)(C + (size_t)row * ldc + col) =
                make_float2(acc[mt][nt][0] + b0, acc[mt][nt][1] + b1);
            *(float2*)(C + (size_t)(row + 8) * ldc + col) =
                make_float2(acc[mt][nt][2] + b0, acc[mt][nt][3] + b1);
        }
}

// ===========================================================================
// proj_fused: ALL THREE projections in one 1536-CTA launch.
// z=0: Q = x@qw+qb (exact FFMA), z=1: K = y@kw+kb (exact FFMA),
// z=2: V = y@vw+vb (3-term tf32 mm_body).
// FFMA path: 128x64 tile, BK=16, double-buffered, 8 rows x 4 cols per thread,
// per-output ascending-k FFMA2 chains (bit-identical to reference GEMM order).
// Dynamic smem: FFMA path uses 24.9KB of the 48KB buffer.
// ===========================================================================
__global__ void __launch_bounds__(256, 2) proj_fused(
    const float* __restrict__ x, const float* __restrict__ y,
    const float* __restrict__ qw, const float* __restrict__ qb,
    const float* __restrict__ kw, const float* __restrict__ kb,
    const float* __restrict__ vw, const float* __restrict__ vb)
{
    extern __shared__ float sm[];
    const int row0 = blockIdx.y * 128, col0 = blockIdx.x * 64;

    if (blockIdx.z == 2) {
        mm_body(y + (size_t)row0 * 512, 512, vw + col0, 512,
                vb + col0, g_Vp + (size_t)row0 * 512 + col0, 512, 512);
        return;
    }

    const float* A    = blockIdx.z ? y  : x;
    const float* W    = blockIdx.z ? kw : qw;
    const float* bias = blockIdx.z ? kb : qb;
    float* C          = blockIdx.z ? g_Kp : g_Qp;

    // As: [2][16][132] at sm, Bs: [2][16][64] at sm + 4224
    float* As = sm;
    float* Bs = sm + 2 * 16 * 132;

    const int tid = threadIdx.x;
    const int ty = tid >> 4, tx = tid & 15;
    const int ar = tid >> 1, ac = (tid & 1) * 8;   // A: row ar, k-cols ac..+7
    const int br = tid >> 4, bc = (tid & 15) * 4;  // B: k-row br, n-cols bc..+3

    const float* Ap = A + (size_t)(row0 + ar) * 512 + ac;
    const float* Wp = W + (size_t)br * 512 + col0 + bc;

    uint64_t acc[8][2];
#pragma unroll
    for (int i = 0; i < 8; i++) { acc[i][0] = 0ull; acc[i][1] = 0ull; }

    float4 a0, a1, b0;
    auto LD = [&](int k0) {
        a0 = *(const float4*)(Ap + k0);
        a1 = *(const float4*)(Ap + k0 + 4);
        b0 = *(const float4*)(Wp + (size_t)k0 * 512);
    };
    auto ST = [&](int s) {
        float* Ab = As + s * 2112;   // 16*132
        Ab[(ac + 0) * 132 + ar] = a0.x; Ab[(ac + 1) * 132 + ar] = a0.y;
        Ab[(ac + 2) * 132 + ar] = a0.z; Ab[(ac + 3) * 132 + ar] = a0.w;
        Ab[(ac + 4) * 132 + ar] = a1.x; Ab[(ac + 5) * 132 + ar] = a1.y;
        Ab[(ac + 6) * 132 + ar] = a1.z; Ab[(ac + 7) * 132 + ar] = a1.w;
        *(float4*)(Bs + s * 1024 + br * 64 + bc) = b0;
    };
    auto CMP = [&](int s) {
        const float* Ab = As + s * 2112;
        const float* Bb = Bs + s * 1024;
#pragma unroll
        for (int kk = 0; kk < 16; kk++) {
            float4 av0 = *(const float4*)(Ab + kk * 132 + ty * 8);
            float4 av1 = *(const float4*)(Ab + kk * 132 + ty * 8 + 4);
            ulonglong2 bv = *(const ulonglong2*)(Bb + kk * 64 + tx * 4);
            uint64_t bp0 = bv.x, bp1 = bv.y;
            float af[8] = {av0.x, av0.y, av0.z, av0.w, av1.x, av1.y, av1.z, av1.w};
#pragma unroll
            for (int i = 0; i < 8; i++) {
                uint64_t ap;
                PACK2(ap, __float_as_uint(af[i]));
                FMA2(acc[i][0], ap, bp0, acc[i][0]);
                FMA2(acc[i][1], ap, bp1, acc[i][1]);
            }
        }
    };

    LD(0);
    ST(0);
    __syncthreads();
    for (int i = 0; i < 32; i++) {
        if (i + 1 < 32) LD((i + 1) * 16);
        CMP(i & 1);
        if (i + 1 < 32) ST((i + 1) & 1);
        __syncthreads();
    }

#pragma unroll
    for (int i = 0; i < 8; i++) {
        int r = row0 + ty * 8 + i;
        int c = col0 + tx * 4;
        uint32_t e0, e1, e2, e3;
        UNPK2(e0, e1, acc[i][0]);
        UNPK2(e2, e3, acc[i][1]);
        float4 w;
        w.x = __uint_as_float(e0) + bias[c + 0];
        w.y = __uint_as_float(e1) + bias[c + 1];
        w.z = __uint_as_float(e2) + bias[c + 2];
        w.w = __uint_as_float(e3) + bias[c + 3];
        *(float4*)(C + (size_t)r * 512 + c) = w;
    }
}

// ===========================================================================
// qk_tf32: S = (Q @ K^T) * NORM on exact Q/K. 4-term split (hh+hl+lh+ll).
// Fused per-(row, 32-col) stat partials. Block tile 128x64x16.
// ===========================================================================
__global__ void __launch_bounds__(256, 2) qk_tf32()
{
    extern __shared__ float sm[];
    const int tid = threadIdx.x;
    const int lane = tid & 31, wid = tid >> 5;
    const int wm = wid & 3, wn = wid >> 2;
    const int inst = blockIdx.z;
    const int row0 = blockIdx.y * 128, col0 = blockIdx.x * 64;
    const float* A = g_Qp + (size_t)inst * 65536 + (size_t)row0 * 64;
    const float* B = g_Kp + (size_t)inst * 65536 + (size_t)col0 * 64;
    float* Sout = g_S + ((size_t)inst << 20) + (size_t)row0 * 1024 + col0;

    int tA[2], rA[2], cA[2];
#pragma unroll
    for (int sl = 0; sl < 2; sl++) {
        int slot = tid + sl * 256;
        tA[sl] = slot >> 5; rA[sl] = (slot & 31) >> 2; cA[sl] = slot & 3;
    }

    float acc[2][4][4];
#pragma unroll
    for (int mt = 0; mt < 2; mt++)
#pragma unroll
        for (int nt = 0; nt < 4; nt++)
#pragma unroll
            for (int e = 0; e < 4; e++) acc[mt][nt][e] = 0.f;

    float ax[2][4], bx[2][2];

    auto LDF = [&](int kb) {
#pragma unroll
        for (int sl = 0; sl < 2; sl++) {
            int tm = tA[sl] & 7, tk = tA[sl] >> 3;
            const float* p = A + (size_t)(tm * 16 + rA[sl]) * 64 + kb + tk * 8 + cA[sl];
            const float* q = p + 8 * 64;
            ax[sl][0] = p[0]; ax[sl][1] = q[0];
            ax[sl][2] = p[4]; ax[sl][3] = q[4];
        }
#pragma unroll
        for (int sl = 0; sl < 2; sl++) {
            int tn = tA[sl] & 7, tk = tA[sl] >> 3;
            const float* p = B + (size_t)(tn * 8 + rA[sl]) * 64 + kb + tk * 8 + cA[sl];
            bx[sl][0] = p[0]; bx[sl][1] = p[4];
        }
    };

    auto STF = [&](int s) {
        float* base = sm + s * 6144;
#pragma unroll
        for (int sl = 0; sl < 2; sl++) {
            float4 h, l;
            h.x = tf32r(ax[sl][0]); l.x = tf32r(ax[sl][0] - h.x);
            h.y = tf32r(ax[sl][1]); l.y = tf32r(ax[sl][1] - h.y);
            h.z = tf32r(ax[sl][2]); l.z = tf32r(ax[sl][2] - h.z);
            h.w = tf32r(ax[sl][3]); l.w = tf32r(ax[sl][3] - h.w);
            int slot = tid + sl * 256;
            int off = (slot >> 5) * 128 + (slot & 31) * 4;
            *(float4*)(base + off) = h;
            *(float4*)(base + 2048 + off) = l;
        }
#pragma unroll
        for (int sl = 0; sl < 2; sl++) {
            float2 h, l;
            h.x = tf32r(bx[sl][0]); l.x = tf32r(bx[sl][0] - h.x);
            h.y = tf32r(bx[sl][1]); l.y = tf32r(bx[sl][1] - h.y);
            int slot = tid + sl * 256;
            int off = (slot >> 5) * 64 + (slot & 31) * 2;
            *(float2*)(base + 4096 + off) = h;
            *(float2*)(base + 5120 + off) = l;
        }
    };

    auto CMP = [&](int s) {
        const float* base = sm + s * 6144;
#pragma unroll
        for (int tk = 0; tk < 2; tk++) {
            uint4 ah[2], al[2];
            uint2 bh[4], bl[4];
#pragma unroll
            for (int mt = 0; mt < 2; mt++) {
                int tg = tk * 8 + wm * 2 + mt;
                ah[mt] = *(const uint4*)(base + tg * 128 + lane * 4);
                al[mt] = *(const uint4*)(base + 2048 + tg * 128 + lane * 4);
            }
#pragma unroll
            for (int nt = 0; nt < 4; nt++) {
                int tg = tk * 8 + wn * 4 + nt;
                bh[nt] = *(const uint2*)(base + 4096 + tg * 64 + lane * 2);
                bl[nt] = *(const uint2*)(base + 5120 + tg * 64 + lane * 2);
            }
#pragma unroll
            for (int mt = 0; mt < 2; mt++)
#pragma unroll
                for (int nt = 0; nt < 4; nt++) {
                    MMA8(acc[mt][nt], (&ah[mt].x), (&bh[nt].x));
                    MMA8(acc[mt][nt], (&ah[mt].x), (&bl[nt].x));
                    MMA8(acc[mt][nt], (&al[mt].x), (&bh[nt].x));
                    MMA8(acc[mt][nt], (&al[mt].x), (&bl[nt].x));
                }
        }
    };

    LDF(0);
    STF(0);
    __syncthreads();
    for (int i = 0; i < 4; i++) {
        if (i + 1 < 4) LDF((i + 1) * 16);
        CMP(i & 1);
        if (i + 1 < 4) STF((i + 1) & 1);
        __syncthreads();
    }

#pragma unroll
    for (int mt = 0; mt < 2; mt++) {
#pragma unroll
        for (int half = 0; half < 2; half++) {
            int row = wm * 32 + mt * 16 + (lane >> 2) + half * 8;
            float v[8];
#pragma unroll
            for (int nt = 0; nt < 4; nt++) {
                v[nt * 2 + 0] = acc[mt][nt][half * 2 + 0] * NORMF;
                v[nt * 2 + 1] = acc[mt][nt][half * 2 + 1] * NORMF;
                int col = wn * 32 + nt * 8 + (lane & 3) * 2;
                *(float2*)(Sout + (size_t)row * 1024 + col) =
                    make_float2(v[nt * 2], v[nt * 2 + 1]);
            }
            float s8 = ((v[0] + v[1]) + (v[2] + v[3])) + ((v[4] + v[5]) + (v[6] + v[7]));
            float m8 = fmaxf(fmaxf(fmaxf(v[0], v[1]), fmaxf(v[2], v[3])),
                             fmaxf(fmaxf(v[4], v[5]), fmaxf(v[6], v[7])));
#pragma unroll
            for (int o = 1; o < 4; o <<= 1) {
                s8 += __shfl_xor_sync(0xffffffffu, s8, o);
                m8 = fmaxf(m8, __shfl_xor_sync(0xffffffffu, m8, o));
            }
            if ((lane & 3) == 0)
                g_part[((size_t)inst * 1024 + row0 + row) * 32 + blockIdx.x * 2 + wn] =
                    make_float2(s8, m8);
        }
    }
}

// Coalesced reduce: 8 threads/row, float4 loads, shfl combine.
__global__ void __launch_bounds__(256) reduce_stats()
{
    int g = blockIdx.x * 256 + threadIdx.x;
    int row = g >> 3, sub = g & 7;
    const float4* p = (const float4*)(g_part + (size_t)row * 32) + sub * 2;
    float4 v0 = p[0], v1 = p[1];
    float s = (v0.x + v0.z) + (v1.x + v1.z);
    float m = fmaxf(fmaxf(v0.y, v0.w), fmaxf(v1.y, v1.w));
#pragma unroll
    for (int o = 1; o < 8; o <<= 1) {
        s += __shfl_xor_sync(0xffffffffu, s, o);
        m = fmaxf(m, __shfl_xor_sync(0xffffffffu, m, o));
    }
    if (sub == 0)
        g_stats2[row] = make_float2(s * (1.0f / 1024.0f), m);
}

__global__ void __launch_bounds__(256, 2) out_mm(
    const float* __restrict__ ow, const float* __restrict__ ob,
    float* __restrict__ out)
{
    int row0 = blockIdx.y * 128, col0 = blockIdx.x * 64;
    mm_body(g_AO + (size_t)row0 * 512, 512, ow + col0, 512,
            ob + col0, out + (size_t)row0 * 512 + col0, 512, 512);
}

// ---------------------------------------------------------------------------
// pv_mm: O = softmax_masked(S) @ V. A hi-only x B hi/lo (2 MMAs per (mt,nt)).
// R8-proven 2-stage pipeline. Inline Z accumulation; 1/Z in epilogue.
// Stage = A-hi(2048) | B-hi(1024) | B-lo(1024) floats = 16KB; 2 stages 32KB.
// ---------------------------------------------------------------------------
__global__ void __launch_bounds__(256, 2) pv_mm()
{
    extern __shared__ float sm[];
    __shared__ float z_sm[128];
    const int tid = threadIdx.x;
    const int lane = tid & 31, wid = tid >> 5;
    const int wm = wid & 3, wn = wid >> 2;
    const int inst = blockIdx.z, row0 = blockIdx.y * 128;
    const float* A = g_S + ((size_t)inst << 20) + (size_t)row0 * 1024;
    const float* B = g_Vp + (size_t)inst * 65536;
    float* C = g_AO + (size_t)inst * 65536 + (size_t)row0 * 64;
    const float2* st = g_stats2 + inst * 1024 + row0;

    int tA[2], rA[2], cA[2], m0s[2];
    float2 st0[2], st1[2];
#pragma unroll
    for (int sl = 0; sl < 2; sl++) {
        int slot = tid + sl * 256;
        tA[sl] = slot >> 5; rA[sl] = (slot & 31) >> 2; cA[sl] = slot & 3;
        m0s[sl] = (tA[sl] & 7) * 16 + rA[sl];
        st0[sl] = st[m0s[sl]];
        st1[sl] = st[m0s[sl] + 8];
    }

    if (tid < 128) z_sm[tid] = 0.f;

    float acc[2][4][4];
#pragma unroll
    for (int mt = 0; mt < 2; mt++)
#pragma unroll
        for (int nt = 0; nt < 4; nt++)
#pragma unroll
            for (int e = 0; e < 4; e++) acc[mt][nt][e] = 0.f;

    float z0[2] = {0.f, 0.f}, z1[2] = {0.f, 0.f};
    float ax[2][4], bx[2][2];

    auto LDF = [&](int kb) {
#pragma unroll
        for (int sl = 0; sl < 2; sl++) {
            int tk = tA[sl] >> 3;
            const float* p = A + (size_t)m0s[sl] * 1024 + kb + tk * 8 + cA[sl];
            const float* q = p + 8 * 1024;
            ax[sl][0] = p[0]; ax[sl][1] = q[0];
            ax[sl][2] = p[4]; ax[sl][3] = q[4];
        }
#pragma unroll
        for (int sl = 0; sl < 2; sl++) {
            int tn = tA[sl] & 7, tk = tA[sl] >> 3;
            int n = tn * 8 + rA[sl];
            int kc = kb + tk * 8 + cA[sl];
            const float* p = B + (size_t)kc * 64 + n;
            bx[sl][0] = p[0]; bx[sl][1] = p[4 * 64];
        }
    };

    auto STF = [&](int s) {
        float* base = sm + s * 4096;
#pragma unroll
        for (int sl = 0; sl < 2; sl++) {
            float p0 = (ax[sl][0] > st0[sl].x) ? __expf(ax[sl][0] - st0[sl].y) : 0.f;
            float p1 = (ax[sl][1] > st1[sl].x) ? __expf(ax[sl][1] - st1[sl].y) : 0.f;
            float p2 = (ax[sl][2] > st0[sl].x) ? __expf(ax[sl][2] - st0[sl].y) : 0.f;
            float p3 = (ax[sl][3] > st1[sl].x) ? __expf(ax[sl][3] - st1[sl].y) : 0.f;
            z0[sl] += p0 + p2;
            z1[sl] += p1 + p3;
            float4 h;
            h.x = tf32r(p0); h.y = tf32r(p1); h.z = tf32r(p2); h.w = tf32r(p3);
            int slot = tid + sl * 256;
            int off = (slot >> 5) * 128 + (slot & 31) * 4;
            *(float4*)(base + off) = h;
        }
#pragma unroll
        for (int sl = 0; sl < 2; sl++) {
            float2 h, l;
            h.x = tf32r(bx[sl][0]); l.x = tf32r(bx[sl][0] - h.x);
            h.y = tf32r(bx[sl][1]); l.y = tf32r(bx[sl][1] - h.y);
            int slot = tid + sl * 256;
            int off = (slot >> 5) * 64 + (slot & 31) * 2;
            *(float2*)(base + 2048 + off) = h;
            *(float2*)(base + 3072 + off) = l;
        }
    };

    auto CMP = [&](int s) {
        const float* base = sm + s * 4096;
#pragma unroll
        for (int tk = 0; tk < 2; tk++) {
            uint4 ah[2];
            uint2 bh[4], bl[4];
#pragma unroll
            for (int mt = 0; mt < 2; mt++) {
                int tg = tk * 8 + wm * 2 + mt;
                ah[mt] = *(const uint4*)(base + tg * 128 + lane * 4);
            }
#pragma unroll
            for (int nt = 0; nt < 4; nt++) {
                int tg = tk * 8 + wn * 4 + nt;
                bh[nt] = *(const uint2*)(base + 2048 + tg * 64 + lane * 2);
                bl[nt] = *(const uint2*)(base + 3072 + tg * 64 + lane * 2);
            }
#pragma unroll
            for (int mt = 0; mt < 2; mt++)
#pragma unroll
                for (int nt = 0; nt < 4; nt++) {
                    MMA8(acc[mt][nt], (&ah[mt].x), (&bh[nt].x));
                    MMA8(acc[mt][nt], (&ah[mt].x), (&bl[nt].x));
                }
        }
    };

    LDF(0);
    STF(0);
    __syncthreads();
    for (int i = 0; i < 64; i++) {
        if (i + 1 < 64) LDF((i + 1) * 16);
        CMP(i & 1);
        if (i + 1 < 64) STF((i + 1) & 1);
        __syncthreads();
    }

#pragma unroll
    for (int sl = 0; sl < 2; sl++) {
        atomicAdd(&z_sm[m0s[sl]], z0[sl]);
        atomicAdd(&z_sm[m0s[sl] + 8], z1[sl]);
    }
    __syncthreads();

#pragma unroll
    for (int mt = 0; mt < 2; mt++)
#pragma unroll
        for (int nt = 0; nt < 4; nt++) {
            int row = wm * 32 + mt * 16 + (lane >> 2);
            int col = wn * 32 + nt * 8 + (lane & 3) * 2;
            float iz0 = 1.0f / z_sm[row];
            float iz1 = 1.0f / z_sm[row + 8];
            *(float2*)(C + (size_t)row * 64 + col) =
                make_float2(acc[mt][nt][0] * iz0, acc[mt][nt][1] * iz0);
            *(float2*)(C + (size_t)(row + 8) * 64 + col) =
                make_float2(acc[mt][nt][2] * iz1, acc[mt][nt][3] * iz1);
        }
}

// ---------------------------------------------------------------------------
extern "C" void kernel_launch(void* const* d_in, const int* in_sizes, int n_in,
                              void* d_out, int out_size)
{
    const float* x  = (const float*)d_in[0];
    const float* y  = (const float*)d_in[1];
    const float* qw = (const float*)d_in[2];
    const float* qb = (const float*)d_in[3];
    const float* kw = (const float*)d_in[4];
    const float* kb = (const float*)d_in[5];
    const float* vw = (const float*)d_in[6];
    const float* vb = (const float*)d_in[7];
    const float* ow = (const float*)d_in[8];
    const float* ob = (const float*)d_in[9];
    float* out = (float*)d_out;

    const int SMB  = 49152;    // mm_body/qk/proj_fused: 48KB dynamic
    const int SMPV = 32768;    // pv: 2 stages * 16KB
    cudaFuncSetAttribute(proj_fused, cudaFuncAttributeMaxDynamicSharedMemorySize, SMB);
    cudaFuncSetAttribute(qk_tf32,    cudaFuncAttributeMaxDynamicSharedMemorySize, SMB);
    cudaFuncSetAttribute(pv_mm,      cudaFuncAttributeMaxDynamicSharedMemorySize, SMPV);
    cudaFuncSetAttribute(out_mm,     cudaFuncAttributeMaxDynamicSharedMemorySize, SMB);

    proj_fused<<<dim3(8, 64, 3), 256, SMB>>>(x, y, qw, qb, kw, kb, vw, vb);
    qk_tf32<<<dim3(16, 8, 64), 256, SMB>>>();
    reduce_stats<<<2048, 256>>>();
    pv_mm<<<dim3(1, 8, 64), 256, SMPV>>>();
    out_mm<<<dim3(8, 64, 1), 256, SMB>>>(ow, ob, out);
}

// round 13
// speedup vs baseline: 1.1777x; 1.0550x over previous
#include <cuda_runtime.h>
#include <cstdint>

// ---------------------------------------------------------------------------
// 64 attention instances: instance i uses contiguous slab [i*65536,(i+1)*65536)
// of each projection viewed as (1024,64).
// Accuracy laws (R3-R12, empirically settled):
//  - Q/K proj: EXACT ascending-k fp32 FFMA, bit-matching reference.
//  - QK^T: 4-term tf32 split (hh+hl+lh+ll) on exact Q/K: clean.
//  - V-proj/out: 3-term split; PV: 2-term (A hi-only) -> ~3.4e-4 smooth.
// This round: B-operand hi/lo planes interleaved as float4 in smem
// (16 LDS.64 -> 8 LDS.128 per iter in pv/qk/mm_body). Values and MMA order
// unchanged -> output bit-identical to R8/R12.
// ---------------------------------------------------------------------------
#define NORMF 0.04419417382415922f   // 1/sqrt(512)

static __device__ float g_Qp[8192 * 512];
static __device__ float g_Kp[8192 * 512];
static __device__ float g_Vp[8192 * 512];
static __device__ float g_AO[8192 * 512];
static __device__ float g_S[67108864];        // 64*1024*1024 scores
static __device__ float2 g_part[65536 * 32];  // per (row, 32-col block): sum, max
static __device__ float2 g_stats2[65536];     // per row: mean, max

#define FMA2(d, a, b, c) \
    asm("fma.rn.f32x2 %0, %1, %2, %3;" : "=l"(d) : "l"(a), "l"(b), "l"(c))
#define PACK2(d, x) \
    asm("mov.b64 %0, {%1, %1};" : "=l"(d) : "r"(x))
#define UNPK2(lo, hi, d) \
    asm("mov.b64 {%0, %1}, %2;" : "=r"(lo), "=r"(hi) : "l"(d))

__device__ __forceinline__ float tf32r(float x) {
    uint32_t u;
    asm("cvt.rna.tf32.f32 %0, %1;" : "=r"(u) : "f"(x));
    return __uint_as_float(u);
}

#define MMA8(d, a, b)                                                          \
    asm volatile("mma.sync.aligned.m16n8k8.row.col.f32.tf32.tf32.f32 "         \
                 "{%0,%1,%2,%3}, {%4,%5,%6,%7}, {%8,%9}, {%0,%1,%2,%3};"       \
                 : "+f"((d)[0]), "+f"((d)[1]), "+f"((d)[2]), "+f"((d)[3])      \
                 : "r"((a)[0]), "r"((a)[1]), "r"((a)[2]), "r"((a)[3]),         \
                   "r"((b)[0]), "r"((b)[1]))

// ===========================================================================
// mm_body: 3xTF32 split GEMM (V-proj, out). B is K x 64 (B[k][n]).
// Block tile 128x64x16, 256 thr, 8 warps (4m x 2n).
// B planes INTERLEAVED: [16 tiles][32 lanes][4] = {h0,h1,l0,l1}.
// Stage = A-hi(2048)+A-lo(2048)+B(2048) = 6144 floats (24KB); 2 stages.
// ===========================================================================
__device__ __forceinline__ void mm_body(
    const float* __restrict__ A, int lda,
    const float* __restrict__ B, int ldb,
    const float* __restrict__ bias,
    float* __restrict__ C, int ldc, int ktot)
{
    extern __shared__ float sm[];
    const int tid = threadIdx.x;
    const int lane = tid & 31, wid = tid >> 5;
    const int wm = wid & 3, wn = wid >> 2;

    int tA[2], rA[2], cA[2];
#pragma unroll
    for (int sl = 0; sl < 2; sl++) {
        int slot = tid + sl * 256;
        tA[sl] = slot >> 5; rA[sl] = (slot & 31) >> 2; cA[sl] = slot & 3;
    }

    float acc[2][4][4];
#pragma unroll
    for (int mt = 0; mt < 2; mt++)
#pragma unroll
        for (int nt = 0; nt < 4; nt++)
#pragma unroll
            for (int e = 0; e < 4; e++) acc[mt][nt][e] = 0.f;

    float ax[2][4], bx[2][2];

    auto LDF = [&](int kb) {
#pragma unroll
        for (int sl = 0; sl < 2; sl++) {
            int tm = tA[sl] & 7, tk = tA[sl] >> 3;
            const float* p = A + (size_t)(tm * 16 + rA[sl]) * lda + kb + tk * 8 + cA[sl];
            const float* q = p + 8 * (size_t)lda;
            ax[sl][0] = p[0]; ax[sl][1] = q[0];
            ax[sl][2] = p[4]; ax[sl][3] = q[4];
        }
#pragma unroll
        for (int sl = 0; sl < 2; sl++) {
            int tn = tA[sl] & 7, tk = tA[sl] >> 3;
            int n = tn * 8 + rA[sl];
            int kc = kb + tk * 8 + cA[sl];
            const float* p = B + (size_t)kc * ldb + n;
            bx[sl][0] = p[0]; bx[sl][1] = p[4 * (size_t)ldb];
        }
    };

    auto STF = [&](int s) {
        float* base = sm + s * 6144;
#pragma unroll
        for (int sl = 0; sl < 2; sl++) {
            float4 h, l;
            h.x = tf32r(ax[sl][0]); l.x = tf32r(ax[sl][0] - h.x);
            h.y = tf32r(ax[sl][1]); l.y = tf32r(ax[sl][1] - h.y);
            h.z = tf32r(ax[sl][2]); l.z = tf32r(ax[sl][2] - h.z);
            h.w = tf32r(ax[sl][3]); l.w = tf32r(ax[sl][3] - h.w);
            int slot = tid + sl * 256;
            int off = (slot >> 5) * 128 + (slot & 31) * 4;
            *(float4*)(base + off) = h;
            *(float4*)(base + 2048 + off) = l;
        }
#pragma unroll
        for (int sl = 0; sl < 2; sl++) {
            float4 v;   // {h0, h1, l0, l1} interleaved
            v.x = tf32r(bx[sl][0]); v.z = tf32r(bx[sl][0] - v.x);
            v.y = tf32r(bx[sl][1]); v.w = tf32r(bx[sl][1] - v.y);
            int slot = tid + sl * 256;
            int off = (slot >> 5) * 128 + (slot & 31) * 4;
            *(float4*)(base + 4096 + off) = v;
        }
    };

    auto CMP = [&](int s) {
        const float* base = sm + s * 6144;
#pragma unroll
        for (int tk = 0; tk < 2; tk++) {
            uint4 ah[2], al[2], bv[4];
#pragma unroll
            for (int mt = 0; mt < 2; mt++) {
                int tg = tk * 8 + wm * 2 + mt;
                ah[mt] = *(const uint4*)(base + tg * 128 + lane * 4);
                al[mt] = *(const uint4*)(base + 2048 + tg * 128 + lane * 4);
            }
#pragma unroll
            for (int nt = 0; nt < 4; nt++) {
                int tg = tk * 8 + wn * 4 + nt;
                bv[nt] = *(const uint4*)(base + 4096 + tg * 128 + lane * 4);
            }
#pragma unroll
            for (int mt = 0; mt < 2; mt++)
#pragma unroll
                for (int nt = 0; nt < 4; nt++) {
                    MMA8(acc[mt][nt], (&ah[mt].x), (&bv[nt].x));
                    MMA8(acc[mt][nt], (&ah[mt].x), (&bv[nt].z));
                    MMA8(acc[mt][nt], (&al[mt].x), (&bv[nt].x));
                }
        }
    };

    const int nk = ktot / 16;
    LDF(0);
    STF(0);
    __syncthreads();
    for (int i = 0; i < nk; i++) {
        if (i + 1 < nk) LDF((i + 1) * 16);
        CMP(i & 1);
        if (i + 1 < nk) STF((i + 1) & 1);
        __syncthreads();
    }

#pragma unroll
    for (int mt = 0; mt < 2; mt++)
#pragma unroll
        for (int nt = 0; nt < 4; nt++) {
            int row = wm * 32 + mt * 16 + (lane >> 2);
            int col = wn * 32 + nt * 8 + (lane & 3) * 2;
            float b0 = bias[col], b1 = bias[col + 1];
            *(float2*)(C + (size_t)row * ldc + col) =
                make_float2(acc[mt][nt][0] + b0, acc[mt][nt][1] + b1);
            *(float2*)(C + (size_t)(row + 8) * ldc + col) =
                make_float2(acc[mt][nt][2] + b0, acc[mt][nt][3] + b1);
        }
}

// ===========================================================================
// proj_fused: ALL THREE projections in one 1536-CTA launch.
// z=0: Q (exact FFMA), z=1: K (exact FFMA), z=2: V (3-term tf32 mm_body).
// ===========================================================================
__global__ void __launch_bounds__(256, 2) proj_fused(
    const float* __restrict__ x, const float* __restrict__ y,
    const float* __restrict__ qw, const float* __restrict__ qb,
    const float* __restrict__ kw, const float* __restrict__ kb,
    const float* __restrict__ vw, const float* __restrict__ vb)
{
    extern __shared__ float sm[];
    const int row0 = blockIdx.y * 128, col0 = blockIdx.x * 64;

    if (blockIdx.z == 2) {
        mm_body(y + (size_t)row0 * 512, 512, vw + col0, 512,
                vb + col0, g_Vp + (size_t)row0 * 512 + col0, 512, 512);
        return;
    }

    const float* A    = blockIdx.z ? y  : x;
    const float* W    = blockIdx.z ? kw : qw;
    const float* bias = blockIdx.z ? kb : qb;
    float* C          = blockIdx.z ? g_Kp : g_Qp;

    float* As = sm;                      // [2][16][132]
    float* Bs = sm + 2 * 16 * 132;       // [2][16][64]

    const int tid = threadIdx.x;
    const int ty = tid >> 4, tx = tid & 15;
    const int ar = tid >> 1, ac = (tid & 1) * 8;
    const int br = tid >> 4, bc = (tid & 15) * 4;

    const float* Ap = A + (size_t)(row0 + ar) * 512 + ac;
    const float* Wp = W + (size_t)br * 512 + col0 + bc;

    uint64_t acc[8][2];
#pragma unroll
    for (int i = 0; i < 8; i++) { acc[i][0] = 0ull; acc[i][1] = 0ull; }

    float4 a0, a1, b0;
    auto LD = [&](int k0) {
        a0 = *(const float4*)(Ap + k0);
        a1 = *(const float4*)(Ap + k0 + 4);
        b0 = *(const float4*)(Wp + (size_t)k0 * 512);
    };
    auto ST = [&](int s) {
        float* Ab = As + s * 2112;
        Ab[(ac + 0) * 132 + ar] = a0.x; Ab[(ac + 1) * 132 + ar] = a0.y;
        Ab[(ac + 2) * 132 + ar] = a0.z; Ab[(ac + 3) * 132 + ar] = a0.w;
        Ab[(ac + 4) * 132 + ar] = a1.x; Ab[(ac + 5) * 132 + ar] = a1.y;
        Ab[(ac + 6) * 132 + ar] = a1.z; Ab[(ac + 7) * 132 + ar] = a1.w;
        *(float4*)(Bs + s * 1024 + br * 64 + bc) = b0;
    };
    auto CMP = [&](int s) {
        const float* Ab = As + s * 2112;
        const float* Bb = Bs + s * 1024;
#pragma unroll
        for (int kk = 0; kk < 16; kk++) {
            float4 av0 = *(const float4*)(Ab + kk * 132 + ty * 8);
            float4 av1 = *(const float4*)(Ab + kk * 132 + ty * 8 + 4);
            ulonglong2 bv = *(const ulonglong2*)(Bb + kk * 64 + tx * 4);
            uint64_t bp0 = bv.x, bp1 = bv.y;
            float af[8] = {av0.x, av0.y, av0.z, av0.w, av1.x, av1.y, av1.z, av1.w};
#pragma unroll
            for (int i = 0; i < 8; i++) {
                uint64_t ap;
                PACK2(ap, __float_as_uint(af[i]));
                FMA2(acc[i][0], ap, bp0, acc[i][0]);
                FMA2(acc[i][1], ap, bp1, acc[i][1]);
            }
        }
    };

    LD(0);
    ST(0);
    __syncthreads();
    for (int i = 0; i < 32; i++) {
        if (i + 1 < 32) LD((i + 1) * 16);
        CMP(i & 1);
        if (i + 1 < 32) ST((i + 1) & 1);
        __syncthreads();
    }

#pragma unroll
    for (int i = 0; i < 8; i++) {
        int r = row0 + ty * 8 + i;
        int c = col0 + tx * 4;
        uint32_t e0, e1, e2, e3;
        UNPK2(e0, e1, acc[i][0]);
        UNPK2(e2, e3, acc[i][1]);
        float4 w;
        w.x = __uint_as_float(e0) + bias[c + 0];
        w.y = __uint_as_float(e1) + bias[c + 1];
        w.z = __uint_as_float(e2) + bias[c + 2];
        w.w = __uint_as_float(e3) + bias[c + 3];
        *(float4*)(C + (size_t)r * 512 + c) = w;
    }
}

// ===========================================================================
// qk_tf32: S = (Q @ K^T) * NORM on exact Q/K. 4-term split (hh+hl+lh+ll).
// B planes interleaved as float4. Fused per-(row, 32-col) stat partials.
// ===========================================================================
__global__ void __launch_bounds__(256, 2) qk_tf32()
{
    extern __shared__ float sm[];
    const int tid = threadIdx.x;
    const int lane = tid & 31, wid = tid >> 5;
    const int wm = wid & 3, wn = wid >> 2;
    const int inst = blockIdx.z;
    const int row0 = blockIdx.y * 128, col0 = blockIdx.x * 64;
    const float* A = g_Qp + (size_t)inst * 65536 + (size_t)row0 * 64;
    const float* B = g_Kp + (size_t)inst * 65536 + (size_t)col0 * 64;
    float* Sout = g_S + ((size_t)inst << 20) + (size_t)row0 * 1024 + col0;

    int tA[2], rA[2], cA[2];
#pragma unroll
    for (int sl = 0; sl < 2; sl++) {
        int slot = tid + sl * 256;
        tA[sl] = slot >> 5; rA[sl] = (slot & 31) >> 2; cA[sl] = slot & 3;
    }

    float acc[2][4][4];
#pragma unroll
    for (int mt = 0; mt < 2; mt++)
#pragma unroll
        for (int nt = 0; nt < 4; nt++)
#pragma unroll
            for (int e = 0; e < 4; e++) acc[mt][nt][e] = 0.f;

    float ax[2][4], bx[2][2];

    auto LDF = [&](int kb) {
#pragma unroll
        for (int sl = 0; sl < 2; sl++) {
            int tm = tA[sl] & 7, tk = tA[sl] >> 3;
            const float* p = A + (size_t)(tm * 16 + rA[sl]) * 64 + kb + tk * 8 + cA[sl];
            const float* q = p + 8 * 64;
            ax[sl][0] = p[0]; ax[sl][1] = q[0];
            ax[sl][2] = p[4]; ax[sl][3] = q[4];
        }
#pragma unroll
        for (int sl = 0; sl < 2; sl++) {
            int tn = tA[sl] & 7, tk = tA[sl] >> 3;
            const float* p = B + (size_t)(tn * 8 + rA[sl]) * 64 + kb + tk * 8 + cA[sl];
            bx[sl][0] = p[0]; bx[sl][1] = p[4];
        }
    };

    auto STF = [&](int s) {
        float* base = sm + s * 6144;
#pragma unroll
        for (int sl = 0; sl < 2; sl++) {
            float4 h, l;
            h.x = tf32r(ax[sl][0]); l.x = tf32r(ax[sl][0] - h.x);
            h.y = tf32r(ax[sl][1]); l.y = tf32r(ax[sl][1] - h.y);
            h.z = tf32r(ax[sl][2]); l.z = tf32r(ax[sl][2] - h.z);
            h.w = tf32r(ax[sl][3]); l.w = tf32r(ax[sl][3] - h.w);
            int slot = tid + sl * 256;
            int off = (slot >> 5) * 128 + (slot & 31) * 4;
            *(float4*)(base + off) = h;
            *(float4*)(base + 2048 + off) = l;
        }
#pragma unroll
        for (int sl = 0; sl < 2; sl++) {
            float4 v;   // {h0, h1, l0, l1}
            v.x = tf32r(bx[sl][0]); v.z = tf32r(bx[sl][0] - v.x);
            v.y = tf32r(bx[sl][1]); v.w = tf32r(bx[sl][1] - v.y);
            int slot = tid + sl * 256;
            int off = (slot >> 5) * 128 + (slot & 31) * 4;
            *(float4*)(base + 4096 + off) = v;
        }
    };

    auto CMP = [&](int s) {
        const float* base = sm + s * 6144;
#pragma unroll
        for (int tk = 0; tk < 2; tk++) {
            uint4 ah[2], al[2], bv[4];
#pragma unroll
            for (int mt = 0; mt < 2; mt++) {
                int tg = tk * 8 + wm * 2 + mt;
                ah[mt] = *(const uint4*)(base + tg * 128 + lane * 4);
                al[mt] = *(const uint4*)(base + 2048 + tg * 128 + lane * 4);
            }
#pragma unroll
            for (int nt = 0; nt < 4; nt++) {
                int tg = tk * 8 + wn * 4 + nt;
                bv[nt] = *(const uint4*)(base + 4096 + tg * 128 + lane * 4);
            }
#pragma unroll
            for (int mt = 0; mt < 2; mt++)
#pragma unroll
                for (int nt = 0; nt < 4; nt++) {
                    MMA8(acc[mt][nt], (&ah[mt].x), (&bv[nt].x));
                    MMA8(acc[mt][nt], (&ah[mt].x), (&bv[nt].z));
                    MMA8(acc[mt][nt], (&al[mt].x), (&bv[nt].x));
                    MMA8(acc[mt][nt], (&al[mt].x), (&bv[nt].z));
                }
        }
    };

    LDF(0);
    STF(0);
    __syncthreads();
    for (int i = 0; i < 4; i++) {
        if (i + 1 < 4) LDF((i + 1) * 16);
        CMP(i & 1);
        if (i + 1 < 4) STF((i + 1) & 1);
        __syncthreads();
    }

#pragma unroll
    for (int mt = 0; mt < 2; mt++) {
#pragma unroll
        for (int half = 0; half < 2; half++) {
            int row = wm * 32 + mt * 16 + (lane >> 2) + half * 8;
            float v[8];
#pragma unroll
            for (int nt = 0; nt < 4; nt++) {
                v[nt * 2 + 0] = acc[mt][nt][half * 2 + 0] * NORMF;
                v[nt * 2 + 1] = acc[mt][nt][half * 2 + 1] * NORMF;
                int col = wn * 32 + nt * 8 + (lane & 3) * 2;
                *(float2*)(Sout + (size_t)row * 1024 + col) =
                    make_float2(v[nt * 2], v[nt * 2 + 1]);
            }
            float s8 = ((v[0] + v[1]) + (v[2] + v[3])) + ((v[4] + v[5]) + (v[6] + v[7]));
            float m8 = fmaxf(fmaxf(fmaxf(v[0], v[1]), fmaxf(v[2], v[3])),
                             fmaxf(fmaxf(v[4], v[5]), fmaxf(v[6], v[7])));
#pragma unroll
            for (int o = 1; o < 4; o <<= 1) {
                s8 += __shfl_xor_sync(0xffffffffu, s8, o);
                m8 = fmaxf(m8, __shfl_xor_sync(0xffffffffu, m8, o));
            }
            if ((lane & 3) == 0)
                g_part[((size_t)inst * 1024 + row0 + row) * 32 + blockIdx.x * 2 + wn] =
                    make_float2(s8, m8);
        }
    }
}

// Coalesced reduce: 8 threads/row, float4 loads, shfl combine.
__global__ void __launch_bounds__(256) reduce_stats()
{
    int g = blockIdx.x * 256 + threadIdx.x;
    int row = g >> 3, sub = g & 7;
    const float4* p = (const float4*)(g_part + (size_t)row * 32) + sub * 2;
    float4 v0 = p[0], v1 = p[1];
    float s = (v0.x + v0.z) + (v1.x + v1.z);
    float m = fmaxf(fmaxf(v0.y, v0.w), fmaxf(v1.y, v1.w));
#pragma unroll
    for (int o = 1; o < 8; o <<= 1) {
        s += __shfl_xor_sync(0xffffffffu, s, o);
        m = fmaxf(m, __shfl_xor_sync(0xffffffffu, m, o));
    }
    if (sub == 0)
        g_stats2[row] = make_float2(s * (1.0f / 1024.0f), m);
}

__global__ void __launch_bounds__(256, 2) out_mm(
    const float* __restrict__ ow, const float* __restrict__ ob,
    float* __restrict__ out)
{
    int row0 = blockIdx.y * 128, col0 = blockIdx.x * 64;
    mm_body(g_AO + (size_t)row0 * 512, 512, ow + col0, 512,
            ob + col0, out + (size_t)row0 * 512 + col0, 512, 512);
}

// ---------------------------------------------------------------------------
// pv_mm: O = softmax_masked(S) @ V. A hi-only x B hi/lo (2 MMAs per (mt,nt)).
// B planes interleaved as float4 -> half the B LDS instructions.
// Stage = A-hi(2048) | B-interleaved(2048) floats = 16KB; 2 stages 32KB.
// Inline Z accumulation; 1/Z in epilogue.
// ---------------------------------------------------------------------------
__global__ void __launch_bounds__(256, 2) pv_mm()
{
    extern __shared__ float sm[];
    __shared__ float z_sm[128];
    const int tid = threadIdx.x;
    const int lane = tid & 31, wid = tid >> 5;
    const int wm = wid & 3, wn = wid >> 2;
    const int inst = blockIdx.z, row0 = blockIdx.y * 128;
    const float* A = g_S + ((size_t)inst << 20) + (size_t)row0 * 1024;
    const float* B = g_Vp + (size_t)inst * 65536;
    float* C = g_AO + (size_t)inst * 65536 + (size_t)row0 * 64;
    const float2* st = g_stats2 + inst * 1024 + row0;

    int tA[2], rA[2], cA[2], m0s[2];
    float2 st0[2], st1[2];
#pragma unroll
    for (int sl = 0; sl < 2; sl++) {
        int slot = tid + sl * 256;
        tA[sl] = slot >> 5; rA[sl] = (slot & 31) >> 2; cA[sl] = slot & 3;
        m0s[sl] = (tA[sl] & 7) * 16 + rA[sl];
        st0[sl] = st[m0s[sl]];
        st1[sl] = st[m0s[sl] + 8];
    }

    if (tid < 128) z_sm[tid] = 0.f;

    float acc[2][4][4];
#pragma unroll
    for (int mt = 0; mt < 2; mt++)
#pragma unroll
        for (int nt = 0; nt < 4; nt++)
#pragma unroll
            for (int e = 0; e < 4; e++) acc[mt][nt][e] = 0.f;

    float z0[2] = {0.f, 0.f}, z1[2] = {0.f, 0.f};
    float ax[2][4], bx[2][2];

    auto LDF = [&](int kb) {
#pragma unroll
        for (int sl = 0; sl < 2; sl++) {
            int tk = tA[sl] >> 3;
            const float* p = A + (size_t)m0s[sl] * 1024 + kb + tk * 8 + cA[sl];
            const float* q = p + 8 * 1024;
            ax[sl][0] = p[0]; ax[sl][1] = q[0];
            ax[sl][2] = p[4]; ax[sl][3] = q[4];
        }
#pragma unroll
        for (int sl = 0; sl < 2; sl++) {
            int tn = tA[sl] & 7, tk = tA[sl] >> 3;
            int n = tn * 8 + rA[sl];
            int kc = kb + tk * 8 + cA[sl];
            const float* p = B + (size_t)kc * 64 + n;
            bx[sl][0] = p[0]; bx[sl][1] = p[4 * 64];
        }
    };

    auto STF = [&](int s) {
        float* base = sm + s * 4096;
#pragma unroll
        for (int sl = 0; sl < 2; sl++) {
            float p0 = (ax[sl][0] > st0[sl].x) ? __expf(ax[sl][0] - st0[sl].y) : 0.f;
            float p1 = (ax[sl][1] > st1[sl].x) ? __expf(ax[sl][1] - st1[sl].y) : 0.f;
            float p2 = (ax[sl][2] > st0[sl].x) ? __expf(ax[sl][2] - st0[sl].y) : 0.f;
            float p3 = (ax[sl][3] > st1[sl].x) ? __expf(ax[sl][3] - st1[sl].y) : 0.f;
            z0[sl] += p0 + p2;
            z1[sl] += p1 + p3;
            float4 h;
            h.x = tf32r(p0); h.y = tf32r(p1); h.z = tf32r(p2); h.w = tf32r(p3);
            int slot = tid + sl * 256;
            int off = (slot >> 5) * 128 + (slot & 31) * 4;
            *(float4*)(base + off) = h;
        }
#pragma unroll
        for (int sl = 0; sl < 2; sl++) {
            float4 v;   // {h0, h1, l0, l1}
            v.x = tf32r(bx[sl][0]); v.z = tf32r(bx[sl][0] - v.x);
            v.y = tf32r(bx[sl][1]); v.w = tf32r(bx[sl][1] - v.y);
            int slot = tid + sl * 256;
            int off = (slot >> 5) * 128 + (slot & 31) * 4;
            *(float4*)(base + 2048 + off) = v;
        }
    };

    auto CMP = [&](int s) {
        const float* base = sm + s * 4096;
#pragma unroll
        for (int tk = 0; tk < 2; tk++) {
            uint4 ah[2], bv[4];
#pragma unroll
            for (int mt = 0; mt < 2; mt++) {
                int tg = tk * 8 + wm * 2 + mt;
                ah[mt] = *(const uint4*)(base + tg * 128 + lane * 4);
            }
#pragma unroll
            for (int nt = 0; nt < 4; nt++) {
                int tg = tk * 8 + wn * 4 + nt;
                bv[nt] = *(const uint4*)(base + 2048 + tg * 128 + lane * 4);
            }
#pragma unroll
            for (int mt = 0; mt < 2; mt++)
#pragma unroll
                for (int nt = 0; nt < 4; nt++) {
                    MMA8(acc[mt][nt], (&ah[mt].x), (&bv[nt].x));
                    MMA8(acc[mt][nt], (&ah[mt].x), (&bv[nt].z));
                }
        }
    };

    LDF(0);
    STF(0);
    __syncthreads();
    for (int i = 0; i < 64; i++) {
        if (i + 1 < 64) LDF((i + 1) * 16);
        CMP(i & 1);
        if (i + 1 < 64) STF((i + 1) & 1);
        __syncthreads();
    }

#pragma unroll
    for (int sl = 0; sl < 2; sl++) {
        atomicAdd(&z_sm[m0s[sl]], z0[sl]);
        atomicAdd(&z_sm[m0s[sl] + 8], z1[sl]);
    }
    __syncthreads();

#pragma unroll
    for (int mt = 0; mt < 2; mt++)
#pragma unroll
        for (int nt = 0; nt < 4; nt++) {
            int row = wm * 32 + mt * 16 + (lane >> 2);
            int col = wn * 32 + nt * 8 + (lane & 3) * 2;
            float iz0 = 1.0f / z_sm[row];
            float iz1 = 1.0f / z_sm[row + 8];
            *(float2*)(C + (size_t)row * 64 + col) =
                make_float2(acc[mt][nt][0] * iz0, acc[mt][nt][1] * iz0);
            *(float2*)(C + (size_t)(row + 8) * 64 + col) =
                make_float2(acc[mt][nt][2] * iz1, acc[mt][nt][3] * iz1);
        }
}

// ---------------------------------------------------------------------------
extern "C" void kernel_launch(void* const* d_in, const int* in_sizes, int n_in,
                              void* d_out, int out_size)
{
    const float* x  = (const float*)d_in[0];
    const float* y  = (const float*)d_in[1];
    const float* qw = (const float*)d_in[2];
    const float* qb = (const float*)d_in[3];
    const float* kw = (const float*)d_in[4];
    const float* kb = (const float*)d_in[5];
    const float* vw = (const float*)d_in[6];
    const float* vb = (const float*)d_in[7];
    const float* ow = (const float*)d_in[8];
    const float* ob = (const float*)d_in[9];
    float* out = (float*)d_out;

    const int SMB  = 49152;    // mm_body/qk/proj_fused: 48KB dynamic
    const int SMPV = 32768;    // pv: 2 stages * 16KB
    cudaFuncSetAttribute(proj_fused, cudaFuncAttributeMaxDynamicSharedMemorySize, SMB);
    cudaFuncSetAttribute(qk_tf32,    cudaFuncAttributeMaxDynamicSharedMemorySize, SMB);
    cudaFuncSetAttribute(pv_mm,      cudaFuncAttributeMaxDynamicSharedMemorySize, SMPV);
    cudaFuncSetAttribute(out_mm,     cudaFuncAttributeMaxDynamicSharedMemorySize, SMB);

    proj_fused<<<dim3(8, 64, 3), 256, SMB>>>(x, y, qw, qb, kw, kb, vw, vb);
    qk_tf32<<<dim3(16, 8, 64), 256, SMB>>>();
    reduce_stats<<<2048, 256>>>();
    pv_mm<<<dim3(1, 8, 64), 256, SMPV>>>();
    out_mm<<<dim3(8, 64, 1), 256, SMB>>>(ow, ob, out);
}

// round 14
// speedup vs baseline: 1.2307x; 1.0450x over previous
#include <cuda_runtime.h>
#include <cstdint>

// ---------------------------------------------------------------------------
// 64 attention instances: instance i uses contiguous slab [i*65536,(i+1)*65536)
// of each projection viewed as (1024,64).
// Accuracy laws (R3-R13, empirically settled):
//  - Q/K proj: EXACT ascending-k fp32 FFMA, bit-matching reference.
//  - QK^T: 4-term tf32 split (hh+hl+lh+ll) on exact Q/K: clean.
//  - Smooth paths: PV 2-term (A hi-only, ~3.4e-4); this round V-proj and out
//    also 2-term (each ~1.2e-4 independent -> total ~3.8e-4, margin 2.6x).
// reduce_stats fused into pv prologue (bit-identical reduction order).
// ---------------------------------------------------------------------------
#define NORMF 0.04419417382415922f   // 1/sqrt(512)

static __device__ float g_Qp[8192 * 512];
static __device__ float g_Kp[8192 * 512];
static __device__ float g_Vp[8192 * 512];
static __device__ float g_AO[8192 * 512];
static __device__ float g_S[67108864];        // 64*1024*1024 scores
static __device__ float2 g_part[65536 * 32];  // per (row, 32-col block): sum, max

#define FMA2(d, a, b, c) \
    asm("fma.rn.f32x2 %0, %1, %2, %3;" : "=l"(d) : "l"(a), "l"(b), "l"(c))
#define PACK2(d, x) \
    asm("mov.b64 %0, {%1, %1};" : "=l"(d) : "r"(x))
#define UNPK2(lo, hi, d) \
    asm("mov.b64 {%0, %1}, %2;" : "=r"(lo), "=r"(hi) : "l"(d))

__device__ __forceinline__ float tf32r(float x) {
    uint32_t u;
    asm("cvt.rna.tf32.f32 %0, %1;" : "=r"(u) : "f"(x));
    return __uint_as_float(u);
}

#define MMA8(d, a, b)                                                          \
    asm volatile("mma.sync.aligned.m16n8k8.row.col.f32.tf32.tf32.f32 "         \
                 "{%0,%1,%2,%3}, {%4,%5,%6,%7}, {%8,%9}, {%0,%1,%2,%3};"       \
                 : "+f"((d)[0]), "+f"((d)[1]), "+f"((d)[2]), "+f"((d)[3])      \
                 : "r"((a)[0]), "r"((a)[1]), "r"((a)[2]), "r"((a)[3]),         \
                   "r"((b)[0]), "r"((b)[1]))

// ===========================================================================
// mm_body2: 2-term tf32 GEMM (A hi-only x B hi/lo). B is K x 64 (B[k][n]).
// Block tile 128x64x16, 256 thr, 8 warps (4m x 2n).
// B planes INTERLEAVED: [16 tiles][32 lanes][4] = {h0,h1,l0,l1}.
// Stage = A-hi(2048) + B(2048) = 4096 floats (16KB); 2 stages = 32KB.
// ===========================================================================
__device__ __forceinline__ void mm_body2(
    const float* __restrict__ A, int lda,
    const float* __restrict__ B, int ldb,
    const float* __restrict__ bias,
    float* __restrict__ C, int ldc, int ktot)
{
    extern __shared__ float sm[];
    const int tid = threadIdx.x;
    const int lane = tid & 31, wid = tid >> 5;
    const int wm = wid & 3, wn = wid >> 2;

    int tA[2], rA[2], cA[2];
#pragma unroll
    for (int sl = 0; sl < 2; sl++) {
        int slot = tid + sl * 256;
        tA[sl] = slot >> 5; rA[sl] = (slot & 31) >> 2; cA[sl] = slot & 3;
    }

    float acc[2][4][4];
#pragma unroll
    for (int mt = 0; mt < 2; mt++)
#pragma unroll
        for (int nt = 0; nt < 4; nt++)
#pragma unroll
            for (int e = 0; e < 4; e++) acc[mt][nt][e] = 0.f;

    float ax[2][4], bx[2][2];

    auto LDF = [&](int kb) {
#pragma unroll
        for (int sl = 0; sl < 2; sl++) {
            int tm = tA[sl] & 7, tk = tA[sl] >> 3;
            const float* p = A + (size_t)(tm * 16 + rA[sl]) * lda + kb + tk * 8 + cA[sl];
            const float* q = p + 8 * (size_t)lda;
            ax[sl][0] = p[0]; ax[sl][1] = q[0];
            ax[sl][2] = p[4]; ax[sl][3] = q[4];
        }
#pragma unroll
        for (int sl = 0; sl < 2; sl++) {
            int tn = tA[sl] & 7, tk = tA[sl] >> 3;
            int n = tn * 8 + rA[sl];
            int kc = kb + tk * 8 + cA[sl];
            const float* p = B + (size_t)kc * ldb + n;
            bx[sl][0] = p[0]; bx[sl][1] = p[4 * (size_t)ldb];
        }
    };

    auto STF = [&](int s) {
        float* base = sm + s * 4096;
#pragma unroll
        for (int sl = 0; sl < 2; sl++) {
            float4 h;
            h.x = tf32r(ax[sl][0]); h.y = tf32r(ax[sl][1]);
            h.z = tf32r(ax[sl][2]); h.w = tf32r(ax[sl][3]);
            int slot = tid + sl * 256;
            int off = (slot >> 5) * 128 + (slot & 31) * 4;
            *(float4*)(base + off) = h;
        }
#pragma unroll
        for (int sl = 0; sl < 2; sl++) {
            float4 v;   // {h0, h1, l0, l1}
            v.x = tf32r(bx[sl][0]); v.z = tf32r(bx[sl][0] - v.x);
            v.y = tf32r(bx[sl][1]); v.w = tf32r(bx[sl][1] - v.y);
            int slot = tid + sl * 256;
            int off = (slot >> 5) * 128 + (slot & 31) * 4;
            *(float4*)(base + 2048 + off) = v;
        }
    };

    auto CMP = [&](int s) {
        const float* base = sm + s * 4096;
#pragma unroll
        for (int tk = 0; tk < 2; tk++) {
            uint4 ah[2], bv[4];
#pragma unroll
            for (int mt = 0; mt < 2; mt++) {
                int tg = tk * 8 + wm * 2 + mt;
                ah[mt] = *(const uint4*)(base + tg * 128 + lane * 4);
            }
#pragma unroll
            for (int nt = 0; nt < 4; nt++) {
                int tg = tk * 8 + wn * 4 + nt;
                bv[nt] = *(const uint4*)(base + 2048 + tg * 128 + lane * 4);
            }
#pragma unroll
            for (int mt = 0; mt < 2; mt++)
#pragma unroll
                for (int nt = 0; nt < 4; nt++) {
                    MMA8(acc[mt][nt], (&ah[mt].x), (&bv[nt].x));
                    MMA8(acc[mt][nt], (&ah[mt].x), (&bv[nt].z));
                }
        }
    };

    const int nk = ktot / 16;
    LDF(0);
    STF(0);
    __syncthreads();
    for (int i = 0; i < nk; i++) {
        if (i + 1 < nk) LDF((i + 1) * 16);
        CMP(i & 1);
        if (i + 1 < nk) STF((i + 1) & 1);
        __syncthreads();
    }

#pragma unroll
    for (int mt = 0; mt < 2; mt++)
#pragma unroll
        for (int nt = 0; nt < 4; nt++) {
            int row = wm * 32 + mt * 16 + (lane >> 2);
            int col = wn * 32 + nt * 8 + (lane & 3) * 2;
            float b0 = bias[col], b1 = bias[col + 1];
            *(float2*)(C + (size_t)row * ldc + col) =
                make_float2(acc[mt][nt][0] + b0, acc[mt][nt][1] + b1);
            *(float2*)(C + (size_t)(row + 8) * ldc + col) =
                make_float2(acc[mt][nt][2] + b0, acc[mt][nt][3] + b1);
        }
}

// ===========================================================================
// proj_fused: ALL THREE projections in one 1536-CTA launch.
// z=0: Q (exact FFMA), z=1: K (exact FFMA), z=2: V (2-term tf32 mm_body2).
// ===========================================================================
__global__ void __launch_bounds__(256, 2) proj_fused(
    const float* __restrict__ x, const float* __restrict__ y,
    const float* __restrict__ qw, const float* __restrict__ qb,
    const float* __restrict__ kw, const float* __restrict__ kb,
    const float* __restrict__ vw, const float* __restrict__ vb)
{
    extern __shared__ float sm[];
    const int row0 = blockIdx.y * 128, col0 = blockIdx.x * 64;

    if (blockIdx.z == 2) {
        mm_body2(y + (size_t)row0 * 512, 512, vw + col0, 512,
                 vb + col0, g_Vp + (size_t)row0 * 512 + col0, 512, 512);
        return;
    }

    const float* A    = blockIdx.z ? y  : x;
    const float* W    = blockIdx.z ? kw : qw;
    const float* bias = blockIdx.z ? kb : qb;
    float* C          = blockIdx.z ? g_Kp : g_Qp;

    float* As = sm;                      // [2][16][132]
    float* Bs = sm + 2 * 16 * 132;       // [2][16][64]

    const int tid = threadIdx.x;
    const int ty = tid >> 4, tx = tid & 15;
    const int ar = tid >> 1, ac = (tid & 1) * 8;
    const int br = tid >> 4, bc = (tid & 15) * 4;

    const float* Ap = A + (size_t)(row0 + ar) * 512 + ac;
    const float* Wp = W + (size_t)br * 512 + col0 + bc;

    uint64_t acc[8][2];
#pragma unroll
    for (int i = 0; i < 8; i++) { acc[i][0] = 0ull; acc[i][1] = 0ull; }

    float4 a0, a1, b0;
    auto LD = [&](int k0) {
        a0 = *(const float4*)(Ap + k0);
        a1 = *(const float4*)(Ap + k0 + 4);
        b0 = *(const float4*)(Wp + (size_t)k0 * 512);
    };
    auto ST = [&](int s) {
        float* Ab = As + s * 2112;
        Ab[(ac + 0) * 132 + ar] = a0.x; Ab[(ac + 1) * 132 + ar] = a0.y;
        Ab[(ac + 2) * 132 + ar] = a0.z; Ab[(ac + 3) * 132 + ar] = a0.w;
        Ab[(ac + 4) * 132 + ar] = a1.x; Ab[(ac + 5) * 132 + ar] = a1.y;
        Ab[(ac + 6) * 132 + ar] = a1.z; Ab[(ac + 7) * 132 + ar] = a1.w;
        *(float4*)(Bs + s * 1024 + br * 64 + bc) = b0;
    };
    auto CMP = [&](int s) {
        const float* Ab = As + s * 2112;
        const float* Bb = Bs + s * 1024;
#pragma unroll
        for (int kk = 0; kk < 16; kk++) {
            float4 av0 = *(const float4*)(Ab + kk * 132 + ty * 8);
            float4 av1 = *(const float4*)(Ab + kk * 132 + ty * 8 + 4);
            ulonglong2 bv = *(const ulonglong2*)(Bb + kk * 64 + tx * 4);
            uint64_t bp0 = bv.x, bp1 = bv.y;
            float af[8] = {av0.x, av0.y, av0.z, av0.w, av1.x, av1.y, av1.z, av1.w};
#pragma unroll
            for (int i = 0; i < 8; i++) {
                uint64_t ap;
                PACK2(ap, __float_as_uint(af[i]));
                FMA2(acc[i][0], ap, bp0, acc[i][0]);
                FMA2(acc[i][1], ap, bp1, acc[i][1]);
            }
        }
    };

    LD(0);
    ST(0);
    __syncthreads();
    for (int i = 0; i < 32; i++) {
        if (i + 1 < 32) LD((i + 1) * 16);
        CMP(i & 1);
        if (i + 1 < 32) ST((i + 1) & 1);
        __syncthreads();
    }

#pragma unroll
    for (int i = 0; i < 8; i++) {
        int r = row0 + ty * 8 + i;
        int c = col0 + tx * 4;
        uint32_t e0, e1, e2, e3;
        UNPK2(e0, e1, acc[i][0]);
        UNPK2(e2, e3, acc[i][1]);
        float4 w;
        w.x = __uint_as_float(e0) + bias[c + 0];
        w.y = __uint_as_float(e1) + bias[c + 1];
        w.z = __uint_as_float(e2) + bias[c + 2];
        w.w = __uint_as_float(e3) + bias[c + 3];
        *(float4*)(C + (size_t)r * 512 + c) = w;
    }
}

// ===========================================================================
// qk_tf32: S = (Q @ K^T) * NORM on exact Q/K. 4-term split (hh+hl+lh+ll).
// B planes interleaved as float4. Fused per-(row, 32-col) stat partials.
// ===========================================================================
__global__ void __launch_bounds__(256, 2) qk_tf32()
{
    extern __shared__ float sm[];
    const int tid = threadIdx.x;
    const int lane = tid & 31, wid = tid >> 5;
    const int wm = wid & 3, wn = wid >> 2;
    const int inst = blockIdx.z;
    const int row0 = blockIdx.y * 128, col0 = blockIdx.x * 64;
    const float* A = g_Qp + (size_t)inst * 65536 + (size_t)row0 * 64;
    const float* B = g_Kp + (size_t)inst * 65536 + (size_t)col0 * 64;
    float* Sout = g_S + ((size_t)inst << 20) + (size_t)row0 * 1024 + col0;

    int tA[2], rA[2], cA[2];
#pragma unroll
    for (int sl = 0; sl < 2; sl++) {
        int slot = tid + sl * 256;
        tA[sl] = slot >> 5; rA[sl] = (slot & 31) >> 2; cA[sl] = slot & 3;
    }

    float acc[2][4][4];
#pragma unroll
    for (int mt = 0; mt < 2; mt++)
#pragma unroll
        for (int nt = 0; nt < 4; nt++)
#pragma unroll
            for (int e = 0; e < 4; e++) acc[mt][nt][e] = 0.f;

    float ax[2][4], bx[2][2];

    auto LDF = [&](int kb) {
#pragma unroll
        for (int sl = 0; sl < 2; sl++) {
            int tm = tA[sl] & 7, tk = tA[sl] >> 3;
            const float* p = A + (size_t)(tm * 16 + rA[sl]) * 64 + kb + tk * 8 + cA[sl];
            const float* q = p + 8 * 64;
            ax[sl][0] = p[0]; ax[sl][1] = q[0];
            ax[sl][2] = p[4]; ax[sl][3] = q[4];
        }
#pragma unroll
        for (int sl = 0; sl < 2; sl++) {
            int tn = tA[sl] & 7, tk = tA[sl] >> 3;
            const float* p = B + (size_t)(tn * 8 + rA[sl]) * 64 + kb + tk * 8 + cA[sl];
            bx[sl][0] = p[0]; bx[sl][1] = p[4];
        }
    };

    auto STF = [&](int s) {
        float* base = sm + s * 6144;
#pragma unroll
        for (int sl = 0; sl < 2; sl++) {
            float4 h, l;
            h.x = tf32r(ax[sl][0]); l.x = tf32r(ax[sl][0] - h.x);
            h.y = tf32r(ax[sl][1]); l.y = tf32r(ax[sl][1] - h.y);
            h.z = tf32r(ax[sl][2]); l.z = tf32r(ax[sl][2] - h.z);
            h.w = tf32r(ax[sl][3]); l.w = tf32r(ax[sl][3] - h.w);
            int slot = tid + sl * 256;
            int off = (slot >> 5) * 128 + (slot & 31) * 4;
            *(float4*)(base + off) = h;
            *(float4*)(base + 2048 + off) = l;
        }
#pragma unroll
        for (int sl = 0; sl < 2; sl++) {
            float4 v;   // {h0, h1, l0, l1}
            v.x = tf32r(bx[sl][0]); v.z = tf32r(bx[sl][0] - v.x);
            v.y = tf32r(bx[sl][1]); v.w = tf32r(bx[sl][1] - v.y);
            int slot = tid + sl * 256;
            int off = (slot >> 5) * 128 + (slot & 31) * 4;
            *(float4*)(base + 4096 + off) = v;
        }
    };

    auto CMP = [&](int s) {
        const float* base = sm + s * 6144;
#pragma unroll
        for (int tk = 0; tk < 2; tk++) {
            uint4 ah[2], al[2], bv[4];
#pragma unroll
            for (int mt = 0; mt < 2; mt++) {
                int tg = tk * 8 + wm * 2 + mt;
                ah[mt] = *(const uint4*)(base + tg * 128 + lane * 4);
                al[mt] = *(const uint4*)(base + 2048 + tg * 128 + lane * 4);
            }
#pragma unroll
            for (int nt = 0; nt < 4; nt++) {
                int tg = tk * 8 + wn * 4 + nt;
                bv[nt] = *(const uint4*)(base + 4096 + tg * 128 + lane * 4);
            }
#pragma unroll
            for (int mt = 0; mt < 2; mt++)
#pragma unroll
                for (int nt = 0; nt < 4; nt++) {
                    MMA8(acc[mt][nt], (&ah[mt].x), (&bv[nt].x));
                    MMA8(acc[mt][nt], (&ah[mt].x), (&bv[nt].z));
                    MMA8(acc[mt][nt], (&al[mt].x), (&bv[nt].x));
                    MMA8(acc[mt][nt], (&al[mt].x), (&bv[nt].z));
                }
        }
    };

    LDF(0);
    STF(0);
    __syncthreads();
    for (int i = 0; i < 4; i++) {
        if (i + 1 < 4) LDF((i + 1) * 16);
        CMP(i & 1);
        if (i + 1 < 4) STF((i + 1) & 1);
        __syncthreads();
    }

#pragma unroll
    for (int mt = 0; mt < 2; mt++) {
#pragma unroll
        for (int half = 0; half < 2; half++) {
            int row = wm * 32 + mt * 16 + (lane >> 2) + half * 8;
            float v[8];
#pragma unroll
            for (int nt = 0; nt < 4; nt++) {
                v[nt * 2 + 0] = acc[mt][nt][half * 2 + 0] * NORMF;
                v[nt * 2 + 1] = acc[mt][nt][half * 2 + 1] * NORMF;
                int col = wn * 32 + nt * 8 + (lane & 3) * 2;
                *(float2*)(Sout + (size_t)row * 1024 + col) =
                    make_float2(v[nt * 2], v[nt * 2 + 1]);
            }
            float s8 = ((v[0] + v[1]) + (v[2] + v[3])) + ((v[4] + v[5]) + (v[6] + v[7]));
            float m8 = fmaxf(fmaxf(fmaxf(v[0], v[1]), fmaxf(v[2], v[3])),
                             fmaxf(fmaxf(v[4], v[5]), fmaxf(v[6], v[7])));
#pragma unroll
            for (int o = 1; o < 4; o <<= 1) {
                s8 += __shfl_xor_sync(0xffffffffu, s8, o);
                m8 = fmaxf(m8, __shfl_xor_sync(0xffffffffu, m8, o));
            }
            if ((lane & 3) == 0)
                g_part[((size_t)inst * 1024 + row0 + row) * 32 + blockIdx.x * 2 + wn] =
                    make_float2(s8, m8);
        }
    }
}

__global__ void __launch_bounds__(256, 2) out_mm(
    const float* __restrict__ ow, const float* __restrict__ ob,
    float* __restrict__ out)
{
    int row0 = blockIdx.y * 128, col0 = blockIdx.x * 64;
    mm_body2(g_AO + (size_t)row0 * 512, 512, ow + col0, 512,
             ob + col0, out + (size_t)row0 * 512 + col0, 512, 512);
}

// ---------------------------------------------------------------------------
// pv_mm: O = softmax_masked(S) @ V. A hi-only x B hi/lo (2 MMAs per (mt,nt)).
// Prologue computes (mean,max) from g_part partials with BIT-IDENTICAL
// reduction order to the old reduce_stats kernel (fused, one launch fewer).
// Stage = A-hi(2048) | B-interleaved(2048) floats = 16KB; 2 stages 32KB.
// Inline Z accumulation; 1/Z in epilogue.
// ---------------------------------------------------------------------------
__global__ void __launch_bounds__(256, 2) pv_mm()
{
    extern __shared__ float sm[];
    __shared__ float z_sm[128];
    __shared__ float2 s_stats[128];
    const int tid = threadIdx.x;
    const int lane = tid & 31, wid = tid >> 5;
    const int wm = wid & 3, wn = wid >> 2;
    const int inst = blockIdx.z, row0 = blockIdx.y * 128;
    const float* A = g_S + ((size_t)inst << 20) + (size_t)row0 * 1024;
    const float* B = g_Vp + (size_t)inst * 65536;
    float* C = g_AO + (size_t)inst * 65536 + (size_t)row0 * 64;

    // ---- fused stats reduce (order matches old reduce_stats exactly) ----
    if (tid < 128) {
        z_sm[tid] = 0.f;
        const float4* p = (const float4*)(g_part + ((size_t)inst * 1024 + row0 + tid) * 32);
        float ss[8], mm[8];
#pragma unroll
        for (int sub = 0; sub < 8; sub++) {
            float4 v0 = p[sub * 2], v1 = p[sub * 2 + 1];
            ss[sub] = (v0.x + v0.z) + (v1.x + v1.z);
            mm[sub] = fmaxf(fmaxf(v0.y, v0.w), fmaxf(v1.y, v1.w));
        }
        float s = ((ss[0] + ss[1]) + (ss[2] + ss[3])) + ((ss[4] + ss[5]) + (ss[6] + ss[7]));
        float m = fmaxf(fmaxf(fmaxf(mm[0], mm[1]), fmaxf(mm[2], mm[3])),
                        fmaxf(fmaxf(mm[4], mm[5]), fmaxf(mm[6], mm[7])));
        s_stats[tid] = make_float2(s * (1.0f / 1024.0f), m);
    }
    __syncthreads();

    int tA[2], rA[2], cA[2], m0s[2];
    float2 st0[2], st1[2];
#pragma unroll
    for (int sl = 0; sl < 2; sl++) {
        int slot = tid + sl * 256;
        tA[sl] = slot >> 5; rA[sl] = (slot & 31) >> 2; cA[sl] = slot & 3;
        m0s[sl] = (tA[sl] & 7) * 16 + rA[sl];
        st0[sl] = s_stats[m0s[sl]];
        st1[sl] = s_stats[m0s[sl] + 8];
    }

    float acc[2][4][4];
#pragma unroll
    for (int mt = 0; mt < 2; mt++)
#pragma unroll
        for (int nt = 0; nt < 4; nt++)
#pragma unroll
            for (int e = 0; e < 4; e++) acc[mt][nt][e] = 0.f;

    float z0[2] = {0.f, 0.f}, z1[2] = {0.f, 0.f};
    float ax[2][4], bx[2][2];

    auto LDF = [&](int kb) {
#pragma unroll
        for (int sl = 0; sl < 2; sl++) {
            int tk = tA[sl] >> 3;
            const float* p = A + (size_t)m0s[sl] * 1024 + kb + tk * 8 + cA[sl];
            const float* q = p + 8 * 1024;
            ax[sl][0] = p[0]; ax[sl][1] = q[0];
            ax[sl][2] = p[4]; ax[sl][3] = q[4];
        }
#pragma unroll
        for (int sl = 0; sl < 2; sl++) {
            int tn = tA[sl] & 7, tk = tA[sl] >> 3;
            int n = tn * 8 + rA[sl];
            int kc = kb + tk * 8 + cA[sl];
            const float* p = B + (size_t)kc * 64 + n;
            bx[sl][0] = p[0]; bx[sl][1] = p[4 * 64];
        }
    };

    auto STF = [&](int s) {
        float* base = sm + s * 4096;
#pragma unroll
        for (int sl = 0; sl < 2; sl++) {
            float p0 = (ax[sl][0] > st0[sl].x) ? __expf(ax[sl][0] - st0[sl].y) : 0.f;
            float p1 = (ax[sl][1] > st1[sl].x) ? __expf(ax[sl][1] - st1[sl].y) : 0.f;
            float p2 = (ax[sl][2] > st0[sl].x) ? __expf(ax[sl][2] - st0[sl].y) : 0.f;
            float p3 = (ax[sl][3] > st1[sl].x) ? __expf(ax[sl][3] - st1[sl].y) : 0.f;
            z0[sl] += p0 + p2;
            z1[sl] += p1 + p3;
            float4 h;
            h.x = tf32r(p0); h.y = tf32r(p1); h.z = tf32r(p2); h.w = tf32r(p3);
            int slot = tid + sl * 256;
            int off = (slot >> 5) * 128 + (slot & 31) * 4;
            *(float4*)(base + off) = h;
        }
#pragma unroll
        for (int sl = 0; sl < 2; sl++) {
            float4 v;   // {h0, h1, l0, l1}
            v.x = tf32r(bx[sl][0]); v.z = tf32r(bx[sl][0] - v.x);
            v.y = tf32r(bx[sl][1]); v.w = tf32r(bx[sl][1] - v.y);
            int slot = tid + sl * 256;
            int off = (slot >> 5) * 128 + (slot & 31) * 4;
            *(float4*)(base + 2048 + off) = v;
        }
    };

    auto CMP = [&](int s) {
        const float* base = sm + s * 4096;
#pragma unroll
        for (int tk = 0; tk < 2; tk++) {
            uint4 ah[2], bv[4];
#pragma unroll
            for (int mt = 0; mt < 2; mt++) {
                int tg = tk * 8 + wm * 2 + mt;
                ah[mt] = *(const uint4*)(base + tg * 128 + lane * 4);
            }
#pragma unroll
            for (int nt = 0; nt < 4; nt++) {
                int tg = tk * 8 + wn * 4 + nt;
                bv[nt] = *(const uint4*)(base + 2048 + tg * 128 + lane * 4);
            }
#pragma unroll
            for (int mt = 0; mt < 2; mt++)
#pragma unroll
                for (int nt = 0; nt < 4; nt++) {
                    MMA8(acc[mt][nt], (&ah[mt].x), (&bv[nt].x));
                    MMA8(acc[mt][nt], (&ah[mt].x), (&bv[nt].z));
                }
        }
    };

    LDF(0);
    STF(0);
    __syncthreads();
    for (int i = 0; i < 64; i++) {
        if (i + 1 < 64) LDF((i + 1) * 16);
        CMP(i & 1);
        if (i + 1 < 64) STF((i + 1) & 1);
        __syncthreads();
    }

#pragma unroll
    for (int sl = 0; sl < 2; sl++) {
        atomicAdd(&z_sm[m0s[sl]], z0[sl]);
        atomicAdd(&z_sm[m0s[sl] + 8], z1[sl]);
    }
    __syncthreads();

#pragma unroll
    for (int mt = 0; mt < 2; mt++)
#pragma unroll
        for (int nt = 0; nt < 4; nt++) {
            int row = wm * 32 + mt * 16 + (lane >> 2);
            int col = wn * 32 + nt * 8 + (lane & 3) * 2;
            float iz0 = 1.0f / z_sm[row];
            float iz1 = 1.0f / z_sm[row + 8];
            *(float2*)(C + (size_t)row * 64 + col) =
                make_float2(acc[mt][nt][0] * iz0, acc[mt][nt][1] * iz0);
            *(float2*)(C + (size_t)(row + 8) * 64 + col) =
                make_float2(acc[mt][nt][2] * iz1, acc[mt][nt][3] * iz1);
        }
}

// ---------------------------------------------------------------------------
extern "C" void kernel_launch(void* const* d_in, const int* in_sizes, int n_in,
                              void* d_out, int out_size)
{
    const float* x  = (const float*)d_in[0];
    const float* y  = (const float*)d_in[1];
    const float* qw = (const float*)d_in[2];
    const float* qb = (const float*)d_in[3];
    const float* kw = (const float*)d_in[4];
    const float* kb = (const float*)d_in[5];
    const float* vw = (const float*)d_in[6];
    const float* vb = (const float*)d_in[7];
    const float* ow = (const float*)d_in[8];
    const float* ob = (const float*)d_in[9];
    float* out = (float*)d_out;

    const int SMQK = 49152;    // qk: 2 stages * 24KB
    const int SMB2 = 32768;    // mm_body2 / pv / proj_fused: 2 stages * 16KB
    cudaFuncSetAttribute(proj_fused, cudaFuncAttributeMaxDynamicSharedMemorySize, SMB2);
    cudaFuncSetAttribute(qk_tf32,    cudaFuncAttributeMaxDynamicSharedMemorySize, SMQK);
    cudaFuncSetAttribute(pv_mm,      cudaFuncAttributeMaxDynamicSharedMemorySize, SMB2);
    cudaFuncSetAttribute(out_mm,     cudaFuncAttributeMaxDynamicSharedMemorySize, SMB2);

    proj_fused<<<dim3(8, 64, 3), 256, SMB2>>>(x, y, qw, qb, kw, kb, vw, vb);
    qk_tf32<<<dim3(16, 8, 64), 256, SMQK>>>();
    pv_mm<<<dim3(1, 8, 64), 256, SMB2>>>();
    out_mm<<<dim3(8, 64, 1), 256, SMB2>>>(ow, ob, out);
}

// round 15
// speedup vs baseline: 1.2369x; 1.0050x over previous
#include <cuda_runtime.h>
#include <cstdint>

// ---------------------------------------------------------------------------
// 64 attention instances: instance i uses contiguous slab [i*65536,(i+1)*65536)
// of each projection viewed as (1024,64).
// Accuracy laws (R3-R14, empirically settled):
//  - Q/K proj: EXACT ascending-k fp32 FFMA, bit-matching reference.
//  - QK^T: 4-term tf32 split (hh+hl+lh+ll) on exact Q/K: clean.
//  - Smooth paths (V-proj, PV, out): 2-term tf32 -> ~4.5e-4 total, margin 2.2x.
// This round: V-proj CTAs folded into the qk launch (z=64..67) — V-proj has
// no dependency on qk inputs and pv needs V only after qk. Scheduling-only
// change; all numerics byte-identical to R14.
// ---------------------------------------------------------------------------
#define NORMF 0.04419417382415922f   // 1/sqrt(512)

static __device__ float g_Qp[8192 * 512];
static __device__ float g_Kp[8192 * 512];
static __device__ float g_Vp[8192 * 512];
static __device__ float g_AO[8192 * 512];
static __device__ float g_S[67108864];        // 64*1024*1024 scores
static __device__ float2 g_part[65536 * 32];  // per (row, 32-col block): sum, max

#define FMA2(d, a, b, c) \
    asm("fma.rn.f32x2 %0, %1, %2, %3;" : "=l"(d) : "l"(a), "l"(b), "l"(c))
#define PACK2(d, x) \
    asm("mov.b64 %0, {%1, %1};" : "=l"(d) : "r"(x))
#define UNPK2(lo, hi, d) \
    asm("mov.b64 {%0, %1}, %2;" : "=r"(lo), "=r"(hi) : "l"(d))

__device__ __forceinline__ float tf32r(float x) {
    uint32_t u;
    asm("cvt.rna.tf32.f32 %0, %1;" : "=r"(u) : "f"(x));
    return __uint_as_float(u);
}

#define MMA8(d, a, b)                                                          \
    asm volatile("mma.sync.aligned.m16n8k8.row.col.f32.tf32.tf32.f32 "         \
                 "{%0,%1,%2,%3}, {%4,%5,%6,%7}, {%8,%9}, {%0,%1,%2,%3};"       \
                 : "+f"((d)[0]), "+f"((d)[1]), "+f"((d)[2]), "+f"((d)[3])      \
                 : "r"((a)[0]), "r"((a)[1]), "r"((a)[2]), "r"((a)[3]),         \
                   "r"((b)[0]), "r"((b)[1]))

// ===========================================================================
// mm_body2: 2-term tf32 GEMM (A hi-only x B hi/lo). B is K x 64 (B[k][n]).
// Block tile 128x64x16, 256 thr, 8 warps (4m x 2n).
// B planes INTERLEAVED: [16 tiles][32 lanes][4] = {h0,h1,l0,l1}.
// Stage = A-hi(2048) + B(2048) = 4096 floats (16KB); 2 stages = 32KB.
// ===========================================================================
__device__ __forceinline__ void mm_body2(
    const float* __restrict__ A, int lda,
    const float* __restrict__ B, int ldb,
    const float* __restrict__ bias,
    float* __restrict__ C, int ldc, int ktot)
{
    extern __shared__ float sm[];
    const int tid = threadIdx.x;
    const int lane = tid & 31, wid = tid >> 5;
    const int wm = wid & 3, wn = wid >> 2;

    int tA[2], rA[2], cA[2];
#pragma unroll
    for (int sl = 0; sl < 2; sl++) {
        int slot = tid + sl * 256;
        tA[sl] = slot >> 5; rA[sl] = (slot & 31) >> 2; cA[sl] = slot & 3;
    }

    float acc[2][4][4];
#pragma unroll
    for (int mt = 0; mt < 2; mt++)
#pragma unroll
        for (int nt = 0; nt < 4; nt++)
#pragma unroll
            for (int e = 0; e < 4; e++) acc[mt][nt][e] = 0.f;

    float ax[2][4], bx[2][2];

    auto LDF = [&](int kb) {
#pragma unroll
        for (int sl = 0; sl < 2; sl++) {
            int tm = tA[sl] & 7, tk = tA[sl] >> 3;
            const float* p = A + (size_t)(tm * 16 + rA[sl]) * lda + kb + tk * 8 + cA[sl];
            const float* q = p + 8 * (size_t)lda;
            ax[sl][0] = p[0]; ax[sl][1] = q[0];
            ax[sl][2] = p[4]; ax[sl][3] = q[4];
        }
#pragma unroll
        for (int sl = 0; sl < 2; sl++) {
            int tn = tA[sl] & 7, tk = tA[sl] >> 3;
            int n = tn * 8 + rA[sl];
            int kc = kb + tk * 8 + cA[sl];
            const float* p = B + (size_t)kc * ldb + n;
            bx[sl][0] = p[0]; bx[sl][1] = p[4 * (size_t)ldb];
        }
    };

    auto STF = [&](int s) {
        float* base = sm + s * 4096;
#pragma unroll
        for (int sl = 0; sl < 2; sl++) {
            float4 h;
            h.x = tf32r(ax[sl][0]); h.y = tf32r(ax[sl][1]);
            h.z = tf32r(ax[sl][2]); h.w = tf32r(ax[sl][3]);
            int slot = tid + sl * 256;
            int off = (slot >> 5) * 128 + (slot & 31) * 4;
            *(float4*)(base + off) = h;
        }
#pragma unroll
        for (int sl = 0; sl < 2; sl++) {
            float4 v;   // {h0, h1, l0, l1}
            v.x = tf32r(bx[sl][0]); v.z = tf32r(bx[sl][0] - v.x);
            v.y = tf32r(bx[sl][1]); v.w = tf32r(bx[sl][1] - v.y);
            int slot = tid + sl * 256;
            int off = (slot >> 5) * 128 + (slot & 31) * 4;
            *(float4*)(base + 2048 + off) = v;
        }
    };

    auto CMP = [&](int s) {
        const float* base = sm + s * 4096;
#pragma unroll
        for (int tk = 0; tk < 2; tk++) {
            uint4 ah[2], bv[4];
#pragma unroll
            for (int mt = 0; mt < 2; mt++) {
                int tg = tk * 8 + wm * 2 + mt;
                ah[mt] = *(const uint4*)(base + tg * 128 + lane * 4);
            }
#pragma unroll
            for (int nt = 0; nt < 4; nt++) {
                int tg = tk * 8 + wn * 4 + nt;
                bv[nt] = *(const uint4*)(base + 2048 + tg * 128 + lane * 4);
            }
#pragma unroll
            for (int mt = 0; mt < 2; mt++)
#pragma unroll
                for (int nt = 0; nt < 4; nt++) {
                    MMA8(acc[mt][nt], (&ah[mt].x), (&bv[nt].x));
                    MMA8(acc[mt][nt], (&ah[mt].x), (&bv[nt].z));
                }
        }
    };

    const int nk = ktot / 16;
    LDF(0);
    STF(0);
    __syncthreads();
    for (int i = 0; i < nk; i++) {
        if (i + 1 < nk) LDF((i + 1) * 16);
        CMP(i & 1);
        if (i + 1 < nk) STF((i + 1) & 1);
        __syncthreads();
    }

#pragma unroll
    for (int mt = 0; mt < 2; mt++)
#pragma unroll
        for (int nt = 0; nt < 4; nt++) {
            int row = wm * 32 + mt * 16 + (lane >> 2);
            int col = wn * 32 + nt * 8 + (lane & 3) * 2;
            float b0 = bias[col], b1 = bias[col + 1];
            *(float2*)(C + (size_t)row * ldc + col) =
                make_float2(acc[mt][nt][0] + b0, acc[mt][nt][1] + b1);
            *(float2*)(C + (size_t)(row + 8) * ldc + col) =
                make_float2(acc[mt][nt][2] + b0, acc[mt][nt][3] + b1);
        }
}

// ===========================================================================
// proj_qk: Q and K projections (exact FFMA) in one 1024-CTA launch.
// z=0: Q = x@qw+qb, z=1: K = y@kw+kb. 128x64 tile, BK=16, double-buffered,
// per-output ascending-k FFMA2 chains (bit-identical to reference order).
// ===========================================================================
__global__ void __launch_bounds__(256, 2) proj_qk(
    const float* __restrict__ x, const float* __restrict__ y,
    const float* __restrict__ qw, const float* __restrict__ qb,
    const float* __restrict__ kw, const float* __restrict__ kb)
{
    extern __shared__ float sm[];
    const int row0 = blockIdx.y * 128, col0 = blockIdx.x * 64;

    const float* A    = blockIdx.z ? y  : x;
    const float* W    = blockIdx.z ? kw : qw;
    const float* bias = blockIdx.z ? kb : qb;
    float* C          = blockIdx.z ? g_Kp : g_Qp;

    float* As = sm;                      // [2][16][132]
    float* Bs = sm + 2 * 16 * 132;       // [2][16][64]

    const int tid = threadIdx.x;
    const int ty = tid >> 4, tx = tid & 15;
    const int ar = tid >> 1, ac = (tid & 1) * 8;
    const int br = tid >> 4, bc = (tid & 15) * 4;

    const float* Ap = A + (size_t)(row0 + ar) * 512 + ac;
    const float* Wp = W + (size_t)br * 512 + col0 + bc;

    uint64_t acc[8][2];
#pragma unroll
    for (int i = 0; i < 8; i++) { acc[i][0] = 0ull; acc[i][1] = 0ull; }

    float4 a0, a1, b0;
    auto LD = [&](int k0) {
        a0 = *(const float4*)(Ap + k0);
        a1 = *(const float4*)(Ap + k0 + 4);
        b0 = *(const float4*)(Wp + (size_t)k0 * 512);
    };
    auto ST = [&](int s) {
        float* Ab = As + s * 2112;
        Ab[(ac + 0) * 132 + ar] = a0.x; Ab[(ac + 1) * 132 + ar] = a0.y;
        Ab[(ac + 2) * 132 + ar] = a0.z; Ab[(ac + 3) * 132 + ar] = a0.w;
        Ab[(ac + 4) * 132 + ar] = a1.x; Ab[(ac + 5) * 132 + ar] = a1.y;
        Ab[(ac + 6) * 132 + ar] = a1.z; Ab[(ac + 7) * 132 + ar] = a1.w;
        *(float4*)(Bs + s * 1024 + br * 64 + bc) = b0;
    };
    auto CMP = [&](int s) {
        const float* Ab = As + s * 2112;
        const float* Bb = Bs + s * 1024;
#pragma unroll
        for (int kk = 0; kk < 16; kk++) {
            float4 av0 = *(const float4*)(Ab + kk * 132 + ty * 8);
            float4 av1 = *(const float4*)(Ab + kk * 132 + ty * 8 + 4);
            ulonglong2 bv = *(const ulonglong2*)(Bb + kk * 64 + tx * 4);
            uint64_t bp0 = bv.x, bp1 = bv.y;
            float af[8] = {av0.x, av0.y, av0.z, av0.w, av1.x, av1.y, av1.z, av1.w};
#pragma unroll
            for (int i = 0; i < 8; i++) {
                uint64_t ap;
                PACK2(ap, __float_as_uint(af[i]));
                FMA2(acc[i][0], ap, bp0, acc[i][0]);
                FMA2(acc[i][1], ap, bp1, acc[i][1]);
            }
        }
    };

    LD(0);
    ST(0);
    __syncthreads();
    for (int i = 0; i < 32; i++) {
        if (i + 1 < 32) LD((i + 1) * 16);
        CMP(i & 1);
        if (i + 1 < 32) ST((i + 1) & 1);
        __syncthreads();
    }

#pragma unroll
    for (int i = 0; i < 8; i++) {
        int r = row0 + ty * 8 + i;
        int c = col0 + tx * 4;
        uint32_t e0, e1, e2, e3;
        UNPK2(e0, e1, acc[i][0]);
        UNPK2(e2, e3, acc[i][1]);
        float4 w;
        w.x = __uint_as_float(e0) + bias[c + 0];
        w.y = __uint_as_float(e1) + bias[c + 1];
        w.z = __uint_as_float(e2) + bias[c + 2];
        w.w = __uint_as_float(e3) + bias[c + 3];
        *(float4*)(C + (size_t)r * 512 + c) = w;
    }
}

// ===========================================================================
// qk_tf32: z<64 -> S = (Q @ K^T) * NORM (4-term split, fused stat partials).
//          z>=64 -> V-projection CTAs (2-term mm_body2), riding the launch.
// ===========================================================================
__global__ void __launch_bounds__(256, 2) qk_tf32(
    const float* __restrict__ yv,
    const float* __restrict__ vw, const float* __restrict__ vb)
{
    extern __shared__ float sm[];
    const int tid = threadIdx.x;

    if (blockIdx.z >= 64) {
        int flat = (blockIdx.z - 64) * 128 + blockIdx.y * 16 + blockIdx.x;
        int vrow0 = (flat >> 3) * 128, vcol0 = (flat & 7) * 64;
        mm_body2(yv + (size_t)vrow0 * 512, 512, vw + vcol0, 512,
                 vb + vcol0, g_Vp + (size_t)vrow0 * 512 + vcol0, 512, 512);
        return;
    }

    const int lane = tid & 31, wid = tid >> 5;
    const int wm = wid & 3, wn = wid >> 2;
    const int inst = blockIdx.z;
    const int row0 = blockIdx.y * 128, col0 = blockIdx.x * 64;
    const float* A = g_Qp + (size_t)inst * 65536 + (size_t)row0 * 64;
    const float* B = g_Kp + (size_t)inst * 65536 + (size_t)col0 * 64;
    float* Sout = g_S + ((size_t)inst << 20) + (size_t)row0 * 1024 + col0;

    int tA[2], rA[2], cA[2];
#pragma unroll
    for (int sl = 0; sl < 2; sl++) {
        int slot = tid + sl * 256;
        tA[sl] = slot >> 5; rA[sl] = (slot & 31) >> 2; cA[sl] = slot & 3;
    }

    float acc[2][4][4];
#pragma unroll
    for (int mt = 0; mt < 2; mt++)
#pragma unroll
        for (int nt = 0; nt < 4; nt++)
#pragma unroll
            for (int e = 0; e < 4; e++) acc[mt][nt][e] = 0.f;

    float ax[2][4], bx[2][2];

    auto LDF = [&](int kb) {
#pragma unroll
        for (int sl = 0; sl < 2; sl++) {
            int tm = tA[sl] & 7, tk = tA[sl] >> 3;
            const float* p = A + (size_t)(tm * 16 + rA[sl]) * 64 + kb + tk * 8 + cA[sl];
            const float* q = p + 8 * 64;
            ax[sl][0] = p[0]; ax[sl][1] = q[0];
            ax[sl][2] = p[4]; ax[sl][3] = q[4];
        }
#pragma unroll
        for (int sl = 0; sl < 2; sl++) {
            int tn = tA[sl] & 7, tk = tA[sl] >> 3;
            const float* p = B + (size_t)(tn * 8 + rA[sl]) * 64 + kb + tk * 8 + cA[sl];
            bx[sl][0] = p[0]; bx[sl][1] = p[4];
        }
    };

    auto STF = [&](int s) {
        float* base = sm + s * 6144;
#pragma unroll
        for (int sl = 0; sl < 2; sl++) {
            float4 h, l;
            h.x = tf32r(ax[sl][0]); l.x = tf32r(ax[sl][0] - h.x);
            h.y = tf32r(ax[sl][1]); l.y = tf32r(ax[sl][1] - h.y);
            h.z = tf32r(ax[sl][2]); l.z = tf32r(ax[sl][2] - h.z);
            h.w = tf32r(ax[sl][3]); l.w = tf32r(ax[sl][3] - h.w);
            int slot = tid + sl * 256;
            int off = (slot >> 5) * 128 + (slot & 31) * 4;
            *(float4*)(base + off) = h;
            *(float4*)(base + 2048 + off) = l;
        }
#pragma unroll
        for (int sl = 0; sl < 2; sl++) {
            float4 v;   // {h0, h1, l0, l1}
            v.x = tf32r(bx[sl][0]); v.z = tf32r(bx[sl][0] - v.x);
            v.y = tf32r(bx[sl][1]); v.w = tf32r(bx[sl][1] - v.y);
            int slot = tid + sl * 256;
            int off = (slot >> 5) * 128 + (slot & 31) * 4;
            *(float4*)(base + 4096 + off) = v;
        }
    };

    auto CMP = [&](int s) {
        const float* base = sm + s * 6144;
#pragma unroll
        for (int tk = 0; tk < 2; tk++) {
            uint4 ah[2], al[2], bv[4];
#pragma unroll
            for (int mt = 0; mt < 2; mt++) {
                int tg = tk * 8 + wm * 2 + mt;
                ah[mt] = *(const uint4*)(base + tg * 128 + lane * 4);
                al[mt] = *(const uint4*)(base + 2048 + tg * 128 + lane * 4);
            }
#pragma unroll
            for (int nt = 0; nt < 4; nt++) {
                int tg = tk * 8 + wn * 4 + nt;
                bv[nt] = *(const uint4*)(base + 4096 + tg * 128 + lane * 4);
            }
#pragma unroll
            for (int mt = 0; mt < 2; mt++)
#pragma unroll
                for (int nt = 0; nt < 4; nt++) {
                    MMA8(acc[mt][nt], (&ah[mt].x), (&bv[nt].x));
                    MMA8(acc[mt][nt], (&ah[mt].x), (&bv[nt].z));
                    MMA8(acc[mt][nt], (&al[mt].x), (&bv[nt].x));
                    MMA8(acc[mt][nt], (&al[mt].x), (&bv[nt].z));
                }
        }
    };

    LDF(0);
    STF(0);
    __syncthreads();
    for (int i = 0; i < 4; i++) {
        if (i + 1 < 4) LDF((i + 1) * 16);
        CMP(i & 1);
        if (i + 1 < 4) STF((i + 1) & 1);
        __syncthreads();
    }

#pragma unroll
    for (int mt = 0; mt < 2; mt++) {
#pragma unroll
        for (int half = 0; half < 2; half++) {
            int row = wm * 32 + mt * 16 + (lane >> 2) + half * 8;
            float v[8];
#pragma unroll
            for (int nt = 0; nt < 4; nt++) {
                v[nt * 2 + 0] = acc[mt][nt][half * 2 + 0] * NORMF;
                v[nt * 2 + 1] = acc[mt][nt][half * 2 + 1] * NORMF;
                int col = wn * 32 + nt * 8 + (lane & 3) * 2;
                *(float2*)(Sout + (size_t)row * 1024 + col) =
                    make_float2(v[nt * 2], v[nt * 2 + 1]);
            }
            float s8 = ((v[0] + v[1]) + (v[2] + v[3])) + ((v[4] + v[5]) + (v[6] + v[7]));
            float m8 = fmaxf(fmaxf(fmaxf(v[0], v[1]), fmaxf(v[2], v[3])),
                             fmaxf(fmaxf(v[4], v[5]), fmaxf(v[6], v[7])));
#pragma unroll
            for (int o = 1; o < 4; o <<= 1) {
                s8 += __shfl_xor_sync(0xffffffffu, s8, o);
                m8 = fmaxf(m8, __shfl_xor_sync(0xffffffffu, m8, o));
            }
            if ((lane & 3) == 0)
                g_part[((size_t)inst * 1024 + row0 + row) * 32 + blockIdx.x * 2 + wn] =
                    make_float2(s8, m8);
        }
    }
}

__global__ void __launch_bounds__(256, 2) out_mm(
    const float* __restrict__ ow, const float* __restrict__ ob,
    float* __restrict__ out)
{
    int row0 = blockIdx.y * 128, col0 = blockIdx.x * 64;
    mm_body2(g_AO + (size_t)row0 * 512, 512, ow + col0, 512,
             ob + col0, out + (size_t)row0 * 512 + col0, 512, 512);
}

// ---------------------------------------------------------------------------
// pv_mm: O = softmax_masked(S) @ V. A hi-only x B hi/lo (2 MMAs per (mt,nt)).
// Prologue computes (mean,max) from g_part partials (bit-identical order).
// Stage = A-hi(2048) | B-interleaved(2048) floats = 16KB; 2 stages 32KB.
// Inline Z accumulation; 1/Z in epilogue.
// ---------------------------------------------------------------------------
__global__ void __launch_bounds__(256, 2) pv_mm()
{
    extern __shared__ float sm[];
    __shared__ float z_sm[128];
    __shared__ float2 s_stats[128];
    const int tid = threadIdx.x;
    const int lane = tid & 31, wid = tid >> 5;
    const int wm = wid & 3, wn = wid >> 2;
    const int inst = blockIdx.z, row0 = blockIdx.y * 128;
    const float* A = g_S + ((size_t)inst << 20) + (size_t)row0 * 1024;
    const float* B = g_Vp + (size_t)inst * 65536;
    float* C = g_AO + (size_t)inst * 65536 + (size_t)row0 * 64;

    if (tid < 128) {
        z_sm[tid] = 0.f;
        const float4* p = (const float4*)(g_part + ((size_t)inst * 1024 + row0 + tid) * 32);
        float ss[8], mm[8];
#pragma unroll
        for (int sub = 0; sub < 8; sub++) {
            float4 v0 = p[sub * 2], v1 = p[sub * 2 + 1];
            ss[sub] = (v0.x + v0.z) + (v1.x + v1.z);
            mm[sub] = fmaxf(fmaxf(v0.y, v0.w), fmaxf(v1.y, v1.w));
        }
        float s = ((ss[0] + ss[1]) + (ss[2] + ss[3])) + ((ss[4] + ss[5]) + (ss[6] + ss[7]));
        float m = fmaxf(fmaxf(fmaxf(mm[0], mm[1]), fmaxf(mm[2], mm[3])),
                        fmaxf(fmaxf(mm[4], mm[5]), fmaxf(mm[6], mm[7])));
        s_stats[tid] = make_float2(s * (1.0f / 1024.0f), m);
    }
    __syncthreads();

    int tA[2], rA[2], cA[2], m0s[2];
    float2 st0[2], st1[2];
#pragma unroll
    for (int sl = 0; sl < 2; sl++) {
        int slot = tid + sl * 256;
        tA[sl] = slot >> 5; rA[sl] = (slot & 31) >> 2; cA[sl] = slot & 3;
        m0s[sl] = (tA[sl] & 7) * 16 + rA[sl];
        st0[sl] = s_stats[m0s[sl]];
        st1[sl] = s_stats[m0s[sl] + 8];
    }

    float acc[2][4][4];
#pragma unroll
    for (int mt = 0; mt < 2; mt++)
#pragma unroll
        for (int nt = 0; nt < 4; nt++)
#pragma unroll
            for (int e = 0; e < 4; e++) acc[mt][nt][e] = 0.f;

    float z0[2] = {0.f, 0.f}, z1[2] = {0.f, 0.f};
    float ax[2][4], bx[2][2];

    auto LDF = [&](int kb) {
#pragma unroll
        for (int sl = 0; sl < 2; sl++) {
            int tk = tA[sl] >> 3;
            const float* p = A + (size_t)m0s[sl] * 1024 + kb + tk * 8 + cA[sl];
            const float* q = p + 8 * 1024;
            ax[sl][0] = p[0]; ax[sl][1] = q[0];
            ax[sl][2] = p[4]; ax[sl][3] = q[4];
        }
#pragma unroll
        for (int sl = 0; sl < 2; sl++) {
            int tn = tA[sl] & 7, tk = tA[sl] >> 3;
            int n = tn * 8 + rA[sl];
            int kc = kb + tk * 8 + cA[sl];
            const float* p = B + (size_t)kc * 64 + n;
            bx[sl][0] = p[0]; bx[sl][1] = p[4 * 64];
        }
    };

    auto STF = [&](int s) {
        float* base = sm + s * 4096;
#pragma unroll
        for (int sl = 0; sl < 2; sl++) {
            float p0 = (ax[sl][0] > st0[sl].x) ? __expf(ax[sl][0] - st0[sl].y) : 0.f;
            float p1 = (ax[sl][1] > st1[sl].x) ? __expf(ax[sl][1] - st1[sl].y) : 0.f;
            float p2 = (ax[sl][2] > st0[sl].x) ? __expf(ax[sl][2] - st0[sl].y) : 0.f;
            float p3 = (ax[sl][3] > st1[sl].x) ? __expf(ax[sl][3] - st1[sl].y) : 0.f;
            z0[sl] += p0 + p2;
            z1[sl] += p1 + p3;
            float4 h;
            h.x = tf32r(p0); h.y = tf32r(p1); h.z = tf32r(p2); h.w = tf32r(p3);
            int slot = tid + sl * 256;
            int off = (slot >> 5) * 128 + (slot & 31) * 4;
            *(float4*)(base + off) = h;
        }
#pragma unroll
        for (int sl = 0; sl < 2; sl++) {
            float4 v;   // {h0, h1, l0, l1}
            v.x = tf32r(bx[sl][0]); v.z = tf32r(bx[sl][0] - v.x);
            v.y = tf32r(bx[sl][1]); v.w = tf32r(bx[sl][1] - v.y);
            int slot = tid + sl * 256;
            int off = (slot >> 5) * 128 + (slot & 31) * 4;
            *(float4*)(base + 2048 + off) = v;
        }
    };

    auto CMP = [&](int s) {
        const float* base = sm + s * 4096;
#pragma unroll
        for (int tk = 0; tk < 2; tk++) {
            uint4 ah[2], bv[4];
#pragma unroll
            for (int mt = 0; mt < 2; mt++) {
                int tg = tk * 8 + wm * 2 + mt;
                ah[mt] = *(const uint4*)(base + tg * 128 + lane * 4);
            }
#pragma unroll
            for (int nt = 0; nt < 4; nt++) {
                int tg = tk * 8 + wn * 4 + nt;
                bv[nt] = *(const uint4*)(base + 2048 + tg * 128 + lane * 4);
            }
#pragma unroll
            for (int mt = 0; mt < 2; mt++)
#pragma unroll
                for (int nt = 0; nt < 4; nt++) {
                    MMA8(acc[mt][nt], (&ah[mt].x), (&bv[nt].x));
                    MMA8(acc[mt][nt], (&ah[mt].x), (&bv[nt].z));
                }
        }
    };

    LDF(0);
    STF(0);
    __syncthreads();
    for (int i = 0; i < 64; i++) {
        if (i + 1 < 64) LDF((i + 1) * 16);
        CMP(i & 1);
        if (i + 1 < 64) STF((i + 1) & 1);
        __syncthreads();
    }

#pragma unroll
    for (int sl = 0; sl < 2; sl++) {
        atomicAdd(&z_sm[m0s[sl]], z0[sl]);
        atomicAdd(&z_sm[m0s[sl] + 8], z1[sl]);
    }
    __syncthreads();

#pragma unroll
    for (int mt = 0; mt < 2; mt++)
#pragma unroll
        for (int nt = 0; nt < 4; nt++) {
            int row = wm * 32 + mt * 16 + (lane >> 2);
            int col = wn * 32 + nt * 8 + (lane & 3) * 2;
            float iz0 = 1.0f / z_sm[row];
            float iz1 = 1.0f / z_sm[row + 8];
            *(float2*)(C + (size_t)row * 64 + col) =
                make_float2(acc[mt][nt][0] * iz0, acc[mt][nt][1] * iz0);
            *(float2*)(C + (size_t)(row + 8) * 64 + col) =
                make_float2(acc[mt][nt][2] * iz1, acc[mt][nt][3] * iz1);
        }
}

// ---------------------------------------------------------------------------
extern "C" void kernel_launch(void* const* d_in, const int* in_sizes, int n_in,
                              void* d_out, int out_size)
{
    const float* x  = (const float*)d_in[0];
    const float* y  = (const float*)d_in[1];
    const float* qw = (const float*)d_in[2];
    const float* qb = (const float*)d_in[3];
    const float* kw = (const float*)d_in[4];
    const float* kb = (const float*)d_in[5];
    const float* vw = (const float*)d_in[6];
    const float* vb = (const float*)d_in[7];
    const float* ow = (const float*)d_in[8];
    const float* ob = (const float*)d_in[9];
    float* out = (float*)d_out;

    const int SMQK = 49152;    // qk (+embedded V-proj): 48KB dynamic
    const int SMB2 = 32768;    // proj_qk / pv / out
    cudaFuncSetAttribute(proj_qk, cudaFuncAttributeMaxDynamicSharedMemorySize, SMB2);
    cudaFuncSetAttribute(qk_tf32, cudaFuncAttributeMaxDynamicSharedMemorySize, SMQK);
    cudaFuncSetAttribute(pv_mm,   cudaFuncAttributeMaxDynamicSharedMemorySize, SMB2);
    cudaFuncSetAttribute(out_mm,  cudaFuncAttributeMaxDynamicSharedMemorySize, SMB2);

    proj_qk<<<dim3(8, 64, 2), 256, SMB2>>>(x, y, qw, qb, kw, kb);
    qk_tf32<<<dim3(16, 8, 68), 256, SMQK>>>(y, vw, vb);
    pv_mm<<<dim3(1, 8, 64), 256, SMB2>>>();
    out_mm<<<dim3(8, 64, 1), 256, SMB2>>>(ow, ob, out);
}

// round 16
// speedup vs baseline: 1.2378x; 1.0007x over previous
#include <cuda_runtime.h>
#include <cstdint>

// ---------------------------------------------------------------------------
// 64 attention instances: instance i uses contiguous slab [i*65536,(i+1)*65536)
// of each projection viewed as (1024,64).
// Accuracy ledger (all empirically calibrated R3-R15):
//  - Q/K proj: EXACT ascending-k fp32 FFMA (mask-critical, frozen).
//  - QK^T: 3-term tf32 split (hh+hl+lh) -> flip error 2.43e-4 (R7-measured).
//  - Smooth paths (V-proj, PV, out): 2-term tf32 -> 4.48e-4 (R14-measured).
//  - Combined (independent): ~5.1e-4, worst-case 6.9e-4 < 1e-3. Final spend.
// Structure: proj_qk (FFMA) -> qk (+V-proj CTAs riding, fused stat partials)
// -> pv (fused stats reduce, inline Z) -> out.
// ---------------------------------------------------------------------------
#define NORMF 0.04419417382415922f   // 1/sqrt(512)

static __device__ float g_Qp[8192 * 512];
static __device__ float g_Kp[8192 * 512];
static __device__ float g_Vp[8192 * 512];
static __device__ float g_AO[8192 * 512];
static __device__ float g_S[67108864];        // 64*1024*1024 scores
static __device__ float2 g_part[65536 * 32];  // per (row, 32-col block): sum, max

#define FMA2(d, a, b, c) \
    asm("fma.rn.f32x2 %0, %1, %2, %3;" : "=l"(d) : "l"(a), "l"(b), "l"(c))
#define PACK2(d, x) \
    asm("mov.b64 %0, {%1, %1};" : "=l"(d) : "r"(x))
#define UNPK2(lo, hi, d) \
    asm("mov.b64 {%0, %1}, %2;" : "=r"(lo), "=r"(hi) : "l"(d))

__device__ __forceinline__ float tf32r(float x) {
    uint32_t u;
    asm("cvt.rna.tf32.f32 %0, %1;" : "=r"(u) : "f"(x));
    return __uint_as_float(u);
}

#define MMA8(d, a, b)                                                          \
    asm volatile("mma.sync.aligned.m16n8k8.row.col.f32.tf32.tf32.f32 "         \
                 "{%0,%1,%2,%3}, {%4,%5,%6,%7}, {%8,%9}, {%0,%1,%2,%3};"       \
                 : "+f"((d)[0]), "+f"((d)[1]), "+f"((d)[2]), "+f"((d)[3])      \
                 : "r"((a)[0]), "r"((a)[1]), "r"((a)[2]), "r"((a)[3]),         \
                   "r"((b)[0]), "r"((b)[1]))

// ===========================================================================
// mm_body2: 2-term tf32 GEMM (A hi-only x B hi/lo). B is K x 64 (B[k][n]).
// Block tile 128x64x16, 256 thr, 8 warps (4m x 2n).
// B planes INTERLEAVED: [16 tiles][32 lanes][4] = {h0,h1,l0,l1}.
// Stage = A-hi(2048) + B(2048) = 4096 floats (16KB); 2 stages = 32KB.
// ===========================================================================
__device__ __forceinline__ void mm_body2(
    const float* __restrict__ A, int lda,
    const float* __restrict__ B, int ldb,
    const float* __restrict__ bias,
    float* __restrict__ C, int ldc, int ktot)
{
    extern __shared__ float sm[];
    const int tid = threadIdx.x;
    const int lane = tid & 31, wid = tid >> 5;
    const int wm = wid & 3, wn = wid >> 2;

    int tA[2], rA[2], cA[2];
#pragma unroll
    for (int sl = 0; sl < 2; sl++) {
        int slot = tid + sl * 256;
        tA[sl] = slot >> 5; rA[sl] = (slot & 31) >> 2; cA[sl] = slot & 3;
    }

    float acc[2][4][4];
#pragma unroll
    for (int mt = 0; mt < 2; mt++)
#pragma unroll
        for (int nt = 0; nt < 4; nt++)
#pragma unroll
            for (int e = 0; e < 4; e++) acc[mt][nt][e] = 0.f;

    float ax[2][4], bx[2][2];

    auto LDF = [&](int kb) {
#pragma unroll
        for (int sl = 0; sl < 2; sl++) {
            int tm = tA[sl] & 7, tk = tA[sl] >> 3;
            const float* p = A + (size_t)(tm * 16 + rA[sl]) * lda + kb + tk * 8 + cA[sl];
            const float* q = p + 8 * (size_t)lda;
            ax[sl][0] = p[0]; ax[sl][1] = q[0];
            ax[sl][2] = p[4]; ax[sl][3] = q[4];
        }
#pragma unroll
        for (int sl = 0; sl < 2; sl++) {
            int tn = tA[sl] & 7, tk = tA[sl] >> 3;
            int n = tn * 8 + rA[sl];
            int kc = kb + tk * 8 + cA[sl];
            const float* p = B + (size_t)kc * ldb + n;
            bx[sl][0] = p[0]; bx[sl][1] = p[4 * (size_t)ldb];
        }
    };

    auto STF = [&](int s) {
        float* base = sm + s * 4096;
#pragma unroll
        for (int sl = 0; sl < 2; sl++) {
            float4 h;
            h.x = tf32r(ax[sl][0]); h.y = tf32r(ax[sl][1]);
            h.z = tf32r(ax[sl][2]); h.w = tf32r(ax[sl][3]);
            int slot = tid + sl * 256;
            int off = (slot >> 5) * 128 + (slot & 31) * 4;
            *(float4*)(base + off) = h;
        }
#pragma unroll
        for (int sl = 0; sl < 2; sl++) {
            float4 v;   // {h0, h1, l0, l1}
            v.x = tf32r(bx[sl][0]); v.z = tf32r(bx[sl][0] - v.x);
            v.y = tf32r(bx[sl][1]); v.w = tf32r(bx[sl][1] - v.y);
            int slot = tid + sl * 256;
            int off = (slot >> 5) * 128 + (slot & 31) * 4;
            *(float4*)(base + 2048 + off) = v;
        }
    };

    auto CMP = [&](int s) {
        const float* base = sm + s * 4096;
#pragma unroll
        for (int tk = 0; tk < 2; tk++) {
            uint4 ah[2], bv[4];
#pragma unroll
            for (int mt = 0; mt < 2; mt++) {
                int tg = tk * 8 + wm * 2 + mt;
                ah[mt] = *(const uint4*)(base + tg * 128 + lane * 4);
            }
#pragma unroll
            for (int nt = 0; nt < 4; nt++) {
                int tg = tk * 8 + wn * 4 + nt;
                bv[nt] = *(const uint4*)(base + 2048 + tg * 128 + lane * 4);
            }
#pragma unroll
            for (int mt = 0; mt < 2; mt++)
#pragma unroll
                for (int nt = 0; nt < 4; nt++) {
                    MMA8(acc[mt][nt], (&ah[mt].x), (&bv[nt].x));
                    MMA8(acc[mt][nt], (&ah[mt].x), (&bv[nt].z));
                }
        }
    };

    const int nk = ktot / 16;
    LDF(0);
    STF(0);
    __syncthreads();
    for (int i = 0; i < nk; i++) {
        if (i + 1 < nk) LDF((i + 1) * 16);
        CMP(i & 1);
        if (i + 1 < nk) STF((i + 1) & 1);
        __syncthreads();
    }

#pragma unroll
    for (int mt = 0; mt < 2; mt++)
#pragma unroll
        for (int nt = 0; nt < 4; nt++) {
            int row = wm * 32 + mt * 16 + (lane >> 2);
            int col = wn * 32 + nt * 8 + (lane & 3) * 2;
            float b0 = bias[col], b1 = bias[col + 1];
            *(float2*)(C + (size_t)row * ldc + col) =
                make_float2(acc[mt][nt][0] + b0, acc[mt][nt][1] + b1);
            *(float2*)(C + (size_t)(row + 8) * ldc + col) =
                make_float2(acc[mt][nt][2] + b0, acc[mt][nt][3] + b1);
        }
}

// ===========================================================================
// proj_qk: Q and K projections (exact FFMA) in one 1024-CTA launch.
// z=0: Q = x@qw+qb, z=1: K = y@kw+kb. 128x64 tile, BK=16, double-buffered,
// per-output ascending-k FFMA2 chains (bit-identical to reference order).
// ===========================================================================
__global__ void __launch_bounds__(256, 2) proj_qk(
    const float* __restrict__ x, const float* __restrict__ y,
    const float* __restrict__ qw, const float* __restrict__ qb,
    const float* __restrict__ kw, const float* __restrict__ kb)
{
    extern __shared__ float sm[];
    const int row0 = blockIdx.y * 128, col0 = blockIdx.x * 64;

    const float* A    = blockIdx.z ? y  : x;
    const float* W    = blockIdx.z ? kw : qw;
    const float* bias = blockIdx.z ? kb : qb;
    float* C          = blockIdx.z ? g_Kp : g_Qp;

    float* As = sm;                      // [2][16][132]
    float* Bs = sm + 2 * 16 * 132;       // [2][16][64]

    const int tid = threadIdx.x;
    const int ty = tid >> 4, tx = tid & 15;
    const int ar = tid >> 1, ac = (tid & 1) * 8;
    const int br = tid >> 4, bc = (tid & 15) * 4;

    const float* Ap = A + (size_t)(row0 + ar) * 512 + ac;
    const float* Wp = W + (size_t)br * 512 + col0 + bc;

    uint64_t acc[8][2];
#pragma unroll
    for (int i = 0; i < 8; i++) { acc[i][0] = 0ull; acc[i][1] = 0ull; }

    float4 a0, a1, b0;
    auto LD = [&](int k0) {
        a0 = *(const float4*)(Ap + k0);
        a1 = *(const float4*)(Ap + k0 + 4);
        b0 = *(const float4*)(Wp + (size_t)k0 * 512);
    };
    auto ST = [&](int s) {
        float* Ab = As + s * 2112;
        Ab[(ac + 0) * 132 + ar] = a0.x; Ab[(ac + 1) * 132 + ar] = a0.y;
        Ab[(ac + 2) * 132 + ar] = a0.z; Ab[(ac + 3) * 132 + ar] = a0.w;
        Ab[(ac + 4) * 132 + ar] = a1.x; Ab[(ac + 5) * 132 + ar] = a1.y;
        Ab[(ac + 6) * 132 + ar] = a1.z; Ab[(ac + 7) * 132 + ar] = a1.w;
        *(float4*)(Bs + s * 1024 + br * 64 + bc) = b0;
    };
    auto CMP = [&](int s) {
        const float* Ab = As + s * 2112;
        const float* Bb = Bs + s * 1024;
#pragma unroll
        for (int kk = 0; kk < 16; kk++) {
            float4 av0 = *(const float4*)(Ab + kk * 132 + ty * 8);
            float4 av1 = *(const float4*)(Ab + kk * 132 + ty * 8 + 4);
            ulonglong2 bv = *(const ulonglong2*)(Bb + kk * 64 + tx * 4);
            uint64_t bp0 = bv.x, bp1 = bv.y;
            float af[8] = {av0.x, av0.y, av0.z, av0.w, av1.x, av1.y, av1.z, av1.w};
#pragma unroll
            for (int i = 0; i < 8; i++) {
                uint64_t ap;
                PACK2(ap, __float_as_uint(af[i]));
                FMA2(acc[i][0], ap, bp0, acc[i][0]);
                FMA2(acc[i][1], ap, bp1, acc[i][1]);
            }
        }
    };

    LD(0);
    ST(0);
    __syncthreads();
    for (int i = 0; i < 32; i++) {
        if (i + 1 < 32) LD((i + 1) * 16);
        CMP(i & 1);
        if (i + 1 < 32) ST((i + 1) & 1);
        __syncthreads();
    }

#pragma unroll
    for (int i = 0; i < 8; i++) {
        int r = row0 + ty * 8 + i;
        int c = col0 + tx * 4;
        uint32_t e0, e1, e2, e3;
        UNPK2(e0, e1, acc[i][0]);
        UNPK2(e2, e3, acc[i][1]);
        float4 w;
        w.x = __uint_as_float(e0) + bias[c + 0];
        w.y = __uint_as_float(e1) + bias[c + 1];
        w.z = __uint_as_float(e2) + bias[c + 2];
        w.w = __uint_as_float(e3) + bias[c + 3];
        *(float4*)(C + (size_t)r * 512 + c) = w;
    }
}

// ===========================================================================
// qk_tf32: z<64 -> S = (Q @ K^T) * NORM (3-term split hh+hl+lh, fused stat
// partials). z>=64 -> V-projection CTAs (2-term mm_body2), riding the launch.
// ===========================================================================
__global__ void __launch_bounds__(256, 2) qk_tf32(
    const float* __restrict__ yv,
    const float* __restrict__ vw, const float* __restrict__ vb)
{
    extern __shared__ float sm[];
    const int tid = threadIdx.x;

    if (blockIdx.z >= 64) {
        int flat = (blockIdx.z - 64) * 128 + blockIdx.y * 16 + blockIdx.x;
        int vrow0 = (flat >> 3) * 128, vcol0 = (flat & 7) * 64;
        mm_body2(yv + (size_t)vrow0 * 512, 512, vw + vcol0, 512,
                 vb + vcol0, g_Vp + (size_t)vrow0 * 512 + vcol0, 512, 512);
        return;
    }

    const int lane = tid & 31, wid = tid >> 5;
    const int wm = wid & 3, wn = wid >> 2;
    const int inst = blockIdx.z;
    const int row0 = blockIdx.y * 128, col0 = blockIdx.x * 64;
    const float* A = g_Qp + (size_t)inst * 65536 + (size_t)row0 * 64;
    const float* B = g_Kp + (size_t)inst * 65536 + (size_t)col0 * 64;
    float* Sout = g_S + ((size_t)inst << 20) + (size_t)row0 * 1024 + col0;

    int tA[2], rA[2], cA[2];
#pragma unroll
    for (int sl = 0; sl < 2; sl++) {
        int slot = tid + sl * 256;
        tA[sl] = slot >> 5; rA[sl] = (slot & 31) >> 2; cA[sl] = slot & 3;
    }

    float acc[2][4][4];
#pragma unroll
    for (int mt = 0; mt < 2; mt++)
#pragma unroll
        for (int nt = 0; nt < 4; nt++)
#pragma unroll
            for (int e = 0; e < 4; e++) acc[mt][nt][e] = 0.f;

    float ax[2][4], bx[2][2];

    auto LDF = [&](int kb) {
#pragma unroll
        for (int sl = 0; sl < 2; sl++) {
            int tm = tA[sl] & 7, tk = tA[sl] >> 3;
            const float* p = A + (size_t)(tm * 16 + rA[sl]) * 64 + kb + tk * 8 + cA[sl];
            const float* q = p + 8 * 64;
            ax[sl][0] = p[0]; ax[sl][1] = q[0];
            ax[sl][2] = p[4]; ax[sl][3] = q[4];
        }
#pragma unroll
        for (int sl = 0; sl < 2; sl++) {
            int tn = tA[sl] & 7, tk = tA[sl] >> 3;
            const float* p = B + (size_t)(tn * 8 + rA[sl]) * 64 + kb + tk * 8 + cA[sl];
            bx[sl][0] = p[0]; bx[sl][1] = p[4];
        }
    };

    auto STF = [&](int s) {
        float* base = sm + s * 6144;
#pragma unroll
        for (int sl = 0; sl < 2; sl++) {
            float4 h, l;
            h.x = tf32r(ax[sl][0]); l.x = tf32r(ax[sl][0] - h.x);
            h.y = tf32r(ax[sl][1]); l.y = tf32r(ax[sl][1] - h.y);
            h.z = tf32r(ax[sl][2]); l.z = tf32r(ax[sl][2] - h.z);
            h.w = tf32r(ax[sl][3]); l.w = tf32r(ax[sl][3] - h.w);
            int slot = tid + sl * 256;
            int off = (slot >> 5) * 128 + (slot & 31) * 4;
            *(float4*)(base + off) = h;
            *(float4*)(base + 2048 + off) = l;
        }
#pragma unroll
        for (int sl = 0; sl < 2; sl++) {
            float4 v;   // {h0, h1, l0, l1}
            v.x = tf32r(bx[sl][0]); v.z = tf32r(bx[sl][0] - v.x);
            v.y = tf32r(bx[sl][1]); v.w = tf32r(bx[sl][1] - v.y);
            int slot = tid + sl * 256;
            int off = (slot >> 5) * 128 + (slot & 31) * 4;
            *(float4*)(base + 4096 + off) = v;
        }
    };

    auto CMP = [&](int s) {
        const float* base = sm + s * 6144;
#pragma unroll
        for (int tk = 0; tk < 2; tk++) {
            uint4 ah[2], al[2], bv[4];
#pragma unroll
            for (int mt = 0; mt < 2; mt++) {
                int tg = tk * 8 + wm * 2 + mt;
                ah[mt] = *(const uint4*)(base + tg * 128 + lane * 4);
                al[mt] = *(const uint4*)(base + 2048 + tg * 128 + lane * 4);
            }
#pragma unroll
            for (int nt = 0; nt < 4; nt++) {
                int tg = tk * 8 + wn * 4 + nt;
                bv[nt] = *(const uint4*)(base + 4096 + tg * 128 + lane * 4);
            }
#pragma unroll
            for (int mt = 0; mt < 2; mt++)
#pragma unroll
                for (int nt = 0; nt < 4; nt++) {
                    MMA8(acc[mt][nt], (&ah[mt].x), (&bv[nt].x));
                    MMA8(acc[mt][nt], (&ah[mt].x), (&bv[nt].z));
                    MMA8(acc[mt][nt], (&al[mt].x), (&bv[nt].x));
                }
        }
    };

    LDF(0);
    STF(0);
    __syncthreads();
    for (int i = 0; i < 4; i++) {
        if (i + 1 < 4) LDF((i + 1) * 16);
        CMP(i & 1);
        if (i + 1 < 4) STF((i + 1) & 1);
        __syncthreads();
    }

#pragma unroll
    for (int mt = 0; mt < 2; mt++) {
#pragma unroll
        for (int half = 0; half < 2; half++) {
            int row = wm * 32 + mt * 16 + (lane >> 2) + half * 8;
            float v[8];
#pragma unroll
            for (int nt = 0; nt < 4; nt++) {
                v[nt * 2 + 0] = acc[mt][nt][half * 2 + 0] * NORMF;
                v[nt * 2 + 1] = acc[mt][nt][half * 2 + 1] * NORMF;
                int col = wn * 32 + nt * 8 + (lane & 3) * 2;
                *(float2*)(Sout + (size_t)row * 1024 + col) =
                    make_float2(v[nt * 2], v[nt * 2 + 1]);
            }
            float s8 = ((v[0] + v[1]) + (v[2] + v[3])) + ((v[4] + v[5]) + (v[6] + v[7]));
            float m8 = fmaxf(fmaxf(fmaxf(v[0], v[1]), fmaxf(v[2], v[3])),
                             fmaxf(fmaxf(v[4], v[5]), fmaxf(v[6], v[7])));
#pragma unroll
            for (int o = 1; o < 4; o <<= 1) {
                s8 += __shfl_xor_sync(0xffffffffu, s8, o);
                m8 = fmaxf(m8, __shfl_xor_sync(0xffffffffu, m8, o));
            }
            if ((lane & 3) == 0)
                g_part[((size_t)inst * 1024 + row0 + row) * 32 + blockIdx.x * 2 + wn] =
                    make_float2(s8, m8);
        }
    }
}

__global__ void __launch_bounds__(256, 2) out_mm(
    const float* __restrict__ ow, const float* __restrict__ ob,
    float* __restrict__ out)
{
    int row0 = blockIdx.y * 128, col0 = blockIdx.x * 64;
    mm_body2(g_AO + (size_t)row0 * 512, 512, ow + col0, 512,
             ob + col0, out + (size_t)row0 * 512 + col0, 512, 512);
}

// ---------------------------------------------------------------------------
// pv_mm: O = softmax_masked(S) @ V. A hi-only x B hi/lo (2 MMAs per (mt,nt)).
// Prologue computes (mean,max) from g_part partials (bit-identical order).
// Stage = A-hi(2048) | B-interleaved(2048) floats = 16KB; 2 stages 32KB.
// Inline Z accumulation; 1/Z in epilogue.
// ---------------------------------------------------------------------------
__global__ void __launch_bounds__(256, 2) pv_mm()
{
    extern __shared__ float sm[];
    __shared__ float z_sm[128];
    __shared__ float2 s_stats[128];
    const int tid = threadIdx.x;
    const int lane = tid & 31, wid = tid >> 5;
    const int wm = wid & 3, wn = wid >> 2;
    const int inst = blockIdx.z, row0 = blockIdx.y * 128;
    const float* A = g_S + ((size_t)inst << 20) + (size_t)row0 * 1024;
    const float* B = g_Vp + (size_t)inst * 65536;
    float* C = g_AO + (size_t)inst * 65536 + (size_t)row0 * 64;

    if (tid < 128) {
        z_sm[tid] = 0.f;
        const float4* p = (const float4*)(g_part + ((size_t)inst * 1024 + row0 + tid) * 32);
        float ss[8], mm[8];
#pragma unroll
        for (int sub = 0; sub < 8; sub++) {
            float4 v0 = p[sub * 2], v1 = p[sub * 2 + 1];
            ss[sub] = (v0.x + v0.z) + (v1.x + v1.z);
            mm[sub] = fmaxf(fmaxf(v0.y, v0.w), fmaxf(v1.y, v1.w));
        }
        float s = ((ss[0] + ss[1]) + (ss[2] + ss[3])) + ((ss[4] + ss[5]) + (ss[6] + ss[7]));
        float m = fmaxf(fmaxf(fmaxf(mm[0], mm[1]), fmaxf(mm[2], mm[3])),
                        fmaxf(fmaxf(mm[4], mm[5]), fmaxf(mm[6], mm[7])));
        s_stats[tid] = make_float2(s * (1.0f / 1024.0f), m);
    }
    __syncthreads();

    int tA[2], rA[2], cA[2], m0s[2];
    float2 st0[2], st1[2];
#pragma unroll
    for (int sl = 0; sl < 2; sl++) {
        int slot = tid + sl * 256;
        tA[sl] = slot >> 5; rA[sl] = (slot & 31) >> 2; cA[sl] = slot & 3;
        m0s[sl] = (tA[sl] & 7) * 16 + rA[sl];
        st0[sl] = s_stats[m0s[sl]];
        st1[sl] = s_stats[m0s[sl] + 8];
    }

    float acc[2][4][4];
#pragma unroll
    for (int mt = 0; mt < 2; mt++)
#pragma unroll
        for (int nt = 0; nt < 4; nt++)
#pragma unroll
            for (int e = 0; e < 4; e++) acc[mt][nt][e] = 0.f;

    float z0[2] = {0.f, 0.f}, z1[2] = {0.f, 0.f};
    float ax[2][4], bx[2][2];

    auto LDF = [&](int kb) {
#pragma unroll
        for (int sl = 0; sl < 2; sl++) {
            int tk = tA[sl] >> 3;
            const float* p = A + (size_t)m0s[sl] * 1024 + kb + tk * 8 + cA[sl];
            const float* q = p + 8 * 1024;
            ax[sl][0] = p[0]; ax[sl][1] = q[0];
            ax[sl][2] = p[4]; ax[sl][3] = q[4];
        }
#pragma unroll
        for (int sl = 0; sl < 2; sl++) {
            int tn = tA[sl] & 7, tk = tA[sl] >> 3;
            int n = tn * 8 + rA[sl];
            int kc = kb + tk * 8 + cA[sl];
            const float* p = B + (size_t)kc * 64 + n;
            bx[sl][0] = p[0]; bx[sl][1] = p[4 * 64];
        }
    };

    auto STF = [&](int s) {
        float* base = sm + s * 4096;
#pragma unroll
        for (int sl = 0; sl < 2; sl++) {
            float p0 = (ax[sl][0] > st0[sl].x) ? __expf(ax[sl][0] - st0[sl].y) : 0.f;
            float p1 = (ax[sl][1] > st1[sl].x) ? __expf(ax[sl][1] - st1[sl].y) : 0.f;
            float p2 = (ax[sl][2] > st0[sl].x) ? __expf(ax[sl][2] - st0[sl].y) : 0.f;
            float p3 = (ax[sl][3] > st1[sl].x) ? __expf(ax[sl][3] - st1[sl].y) : 0.f;
            z0[sl] += p0 + p2;
            z1[sl] += p1 + p3;
            float4 h;
            h.x = tf32r(p0); h.y = tf32r(p1); h.z = tf32r(p2); h.w = tf32r(p3);
            int slot = tid + sl * 256;
            int off = (slot >> 5) * 128 + (slot & 31) * 4;
            *(float4*)(base + off) = h;
        }
#pragma unroll
        for (int sl = 0; sl < 2; sl++) {
            float4 v;   // {h0, h1, l0, l1}
            v.x = tf32r(bx[sl][0]); v.z = tf32r(bx[sl][0] - v.x);
            v.y = tf32r(bx[sl][1]); v.w = tf32r(bx[sl][1] - v.y);
            int slot = tid + sl * 256;
            int off = (slot >> 5) * 128 + (slot & 31) * 4;
            *(float4*)(base + 2048 + off) = v;
        }
    };

    auto CMP = [&](int s) {
        const float* base = sm + s * 4096;
#pragma unroll
        for (int tk = 0; tk < 2; tk++) {
            uint4 ah[2], bv[4];
#pragma unroll
            for (int mt = 0; mt < 2; mt++) {
                int tg = tk * 8 + wm * 2 + mt;
                ah[mt] = *(const uint4*)(base + tg * 128 + lane * 4);
            }
#pragma unroll
            for (int nt = 0; nt < 4; nt++) {
                int tg = tk * 8 + wn * 4 + nt;
                bv[nt] = *(const uint4*)(base + 2048 + tg * 128 + lane * 4);
            }
#pragma unroll
            for (int mt = 0; mt < 2; mt++)
#pragma unroll
                for (int nt = 0; nt < 4; nt++) {
                    MMA8(acc[mt][nt], (&ah[mt].x), (&bv[nt].x));
                    MMA8(acc[mt][nt], (&ah[mt].x), (&bv[nt].z));
                }
        }
    };

    LDF(0);
    STF(0);
    __syncthreads();
    for (int i = 0; i < 64; i++) {
        if (i + 1 < 64) LDF((i + 1) * 16);
        CMP(i & 1);
        if (i + 1 < 64) STF((i + 1) & 1);
        __syncthreads();
    }

#pragma unroll
    for (int sl = 0; sl < 2; sl++) {
        atomicAdd(&z_sm[m0s[sl]], z0[sl]);
        atomicAdd(&z_sm[m0s[sl] + 8], z1[sl]);
    }
    __syncthreads();

#pragma unroll
    for (int mt = 0; mt < 2; mt++)
#pragma unroll
        for (int nt = 0; nt < 4; nt++) {
            int row = wm * 32 + mt * 16 + (lane >> 2);
            int col = wn * 32 + nt * 8 + (lane & 3) * 2;
            float iz0 = 1.0f / z_sm[row];
            float iz1 = 1.0f / z_sm[row + 8];
            *(float2*)(C + (size_t)row * 64 + col) =
                make_float2(acc[mt][nt][0] * iz0, acc[mt][nt][1] * iz0);
            *(float2*)(C + (size_t)(row + 8) * 64 + col) =
                make_float2(acc[mt][nt][2] * iz1, acc[mt][nt][3] * iz1);
        }
}

// ---------------------------------------------------------------------------
extern "C" void kernel_launch(void* const* d_in, const int* in_sizes, int n_in,
                              void* d_out, int out_size)
{
    const float* x  = (const float*)d_in[0];
    const float* y  = (const float*)d_in[1];
    const float* qw = (const float*)d_in[2];
    const float* qb = (const float*)d_in[3];
    const float* kw = (const float*)d_in[4];
    const float* kb = (const float*)d_in[5];
    const float* vw = (const float*)d_in[6];
    const float* vb = (const float*)d_in[7];
    const float* ow = (const float*)d_in[8];
    const float* ob = (const float*)d_in[9];
    float* out = (float*)d_out;

    const int SMQK = 49152;    // qk (+embedded V-proj): 48KB dynamic
    const int SMB2 = 32768;    // proj_qk / pv / out
    cudaFuncSetAttribute(proj_qk, cudaFuncAttributeMaxDynamicSharedMemorySize, SMB2);
    cudaFuncSetAttribute(qk_tf32, cudaFuncAttributeMaxDynamicSharedMemorySize, SMQK);
    cudaFuncSetAttribute(pv_mm,   cudaFuncAttributeMaxDynamicSharedMemorySize, SMB2);
    cudaFuncSetAttribute(out_mm,  cudaFuncAttributeMaxDynamicSharedMemorySize, SMB2);

    proj_qk<<<dim3(8, 64, 2), 256, SMB2>>>(x, y, qw, qb, kw, kb);
    qk_tf32<<<dim3(16, 8, 68), 256, SMQK>>>(y, vw, vb);
    pv_mm<<<dim3(1, 8, 64), 256, SMB2>>>();
    out_mm<<<dim3(8, 64, 1), 256, SMB2>>>(ow, ob, out);
}